// round 2
// baseline (speedup 1.0000x reference)
#include <cuda_runtime.h>

#define NN 100000
#define EE 1600000
#define EPt 1700000     // EE + NN (with self loops)
#define HC 128          // H*C layer1
#define CC 32
#define EDIM 16

// ---------------- scratch (static device allocations; no cudaMalloc) -------
__device__ __align__(16) float    g_v1e[EDIM * 4];
__device__ __align__(16) float    g_v2e[EDIM];
__device__            float       g_deg[NN];
__device__ __align__(16) float    g_slae1[NN * 4];
__device__            float       g_slae2[NN];
__device__ __align__(16) float    g_ae1[(size_t)EE * 4];
__device__            float       g_ae2[EE];
__device__ __align__(16) float    g_h1f[(size_t)NN * HC];
__device__ __align__(16) float    g_als1[NN * 4];
__device__ __align__(16) float    g_ald1[NN * 4];
__device__ __align__(16) float    g_e1[(size_t)EPt * 4];
__device__            unsigned    g_m1[NN * 4];
__device__            float       g_z1[NN * 4];
__device__ __align__(16) float    g_acc1[(size_t)NN * HC];   // reused as h1 (post-elu)
__device__ __align__(16) float    g_h2f[(size_t)NN * CC];
__device__            float       g_als2[NN];
__device__            float       g_ald2[NN];
__device__            float       g_e2[EPt];
__device__            unsigned    g_m2[NN];
__device__            float       g_z2[NN];
__device__ __align__(16) float    g_acc2[(size_t)NN * CC];

// ---------------- helpers ---------------------------------------------------
__device__ __forceinline__ float lrelu(float x) { return x > 0.f ? x : 0.2f * x; }
__device__ __forceinline__ float elu1(float x)  { return x > 0.f ? x : expm1f(x); }
// order-preserving float<->uint encoding for atomicMax; 0 == encoded(-NaN) <= everything
__device__ __forceinline__ unsigned fenc(float f) {
    unsigned u = __float_as_uint(f);
    return (u & 0x80000000u) ? ~u : (u | 0x80000000u);
}
__device__ __forceinline__ float fdec(unsigned u) {
    return __uint_as_float((u & 0x80000000u) ? (u & 0x7fffffffu) : ~u);
}
__device__ __forceinline__ void red_add_v4(float* addr, float4 v) {
    asm volatile("red.global.add.v4.f32 [%0], {%1,%2,%3,%4};"
                 :: "l"(addr), "f"(v.x), "f"(v.y), "f"(v.z), "f"(v.w) : "memory");
}

// ---------------- tiny precompute: v1e, v2e ---------------------------------
__global__ void k_v(const float* __restrict__ W1e, const float* __restrict__ a1e,
                    const float* __restrict__ W2e, const float* __restrict__ a2e) {
    int t = threadIdx.x;
    if (t < 64) {
        int d = t >> 2, h = t & 3;
        float s = 0.f;
        for (int c = 0; c < 32; c++) s += W1e[d * 128 + h * 32 + c] * a1e[h * 32 + c];
        g_v1e[d * 4 + h] = s;
    } else if (t < 80) {
        int d = t - 64;
        float s = 0.f;
        for (int c = 0; c < 32; c++) s += W2e[d * 32 + c] * a2e[c];
        g_v2e[d] = s;
    }
}

// ---------------- P0: edge-attr logits + self-loop accumulation -------------
__global__ void k_edge_pre(const float* __restrict__ eattr, const int* __restrict__ dst) {
    int e = blockIdx.x * 256 + threadIdx.x;
    if (e >= EE) return;
    float w[16];
    const float4* ep = (const float4*)(eattr + (size_t)e * EDIM);
    *(float4*)&w[0]  = ep[0];
    *(float4*)&w[4]  = ep[1];
    *(float4*)&w[8]  = ep[2];
    *(float4*)&w[12] = ep[3];
    float a0 = 0, a1 = 0, a2 = 0, a3 = 0, b = 0;
#pragma unroll
    for (int j = 0; j < 16; j++) {
        float wv = w[j];
        a0 += wv * __ldg(&g_v1e[j * 4 + 0]);
        a1 += wv * __ldg(&g_v1e[j * 4 + 1]);
        a2 += wv * __ldg(&g_v1e[j * 4 + 2]);
        a3 += wv * __ldg(&g_v1e[j * 4 + 3]);
        b  += wv * __ldg(&g_v2e[j]);
    }
    *(float4*)&g_ae1[(size_t)e * 4] = make_float4(a0, a1, a2, a3);
    g_ae2[e] = b;
    int d = dst[e];
    atomicAdd(&g_deg[d], 1.f);
    atomicAdd(&g_slae1[d * 4 + 0], a0);
    atomicAdd(&g_slae1[d * 4 + 1], a1);
    atomicAdd(&g_slae1[d * 4 + 2], a2);
    atomicAdd(&g_slae1[d * 4 + 3], a3);
    atomicAdd(&g_slae2[d], b);
}

__global__ void k_selfloop() {
    int n = blockIdx.x * 256 + threadIdx.x;
    if (n >= NN) return;
    float inv = 1.f / fmaxf(g_deg[n], 1.f);
    g_slae1[n * 4 + 0] *= inv;
    g_slae1[n * 4 + 1] *= inv;
    g_slae1[n * 4 + 2] *= inv;
    g_slae1[n * 4 + 3] *= inv;
    g_slae2[n] *= inv;
}

// ---------------- GEMM1: h1f = x @ W1 (100000x128 @ 128x128) ----------------
__global__ void k_gemm1(const float* __restrict__ X, const float* __restrict__ W) {
    __shared__ float As[16][64];
    __shared__ float Bs[16][128];
    int tid = threadIdx.x;
    int brow = blockIdx.x * 64;
    int tr8 = (tid >> 5) * 8;
    int tc4 = (tid & 31) * 4;
    float acc[8][4];
#pragma unroll
    for (int i = 0; i < 8; i++)
#pragma unroll
        for (int j = 0; j < 4; j++) acc[i][j] = 0.f;

    int lm = tid >> 2;
    int lkq = (tid & 3) * 4;
    int lkr = tid >> 5;
    int lnc = (tid & 31) * 4;

    for (int k0 = 0; k0 < 128; k0 += 16) {
        int gr = brow + lm;
        float4 av = (gr < NN) ? *(const float4*)&X[(size_t)gr * 128 + k0 + lkq]
                              : make_float4(0, 0, 0, 0);
        As[lkq + 0][lm] = av.x;
        As[lkq + 1][lm] = av.y;
        As[lkq + 2][lm] = av.z;
        As[lkq + 3][lm] = av.w;
        *(float4*)&Bs[lkr][lnc]     = *(const float4*)&W[(size_t)(k0 + lkr) * 128 + lnc];
        *(float4*)&Bs[lkr + 8][lnc] = *(const float4*)&W[(size_t)(k0 + lkr + 8) * 128 + lnc];
        __syncthreads();
#pragma unroll
        for (int k = 0; k < 16; k++) {
            float4 bv = *(float4*)&Bs[k][tc4];
            float a[8];
#pragma unroll
            for (int i = 0; i < 8; i++) a[i] = As[k][tr8 + i];
#pragma unroll
            for (int i = 0; i < 8; i++) {
                acc[i][0] += a[i] * bv.x;
                acc[i][1] += a[i] * bv.y;
                acc[i][2] += a[i] * bv.z;
                acc[i][3] += a[i] * bv.w;
            }
        }
        __syncthreads();
    }
#pragma unroll
    for (int i = 0; i < 8; i++) {
        int row = brow + tr8 + i;
        if (row < NN)
            *(float4*)&g_h1f[(size_t)row * 128 + tc4] =
                make_float4(acc[i][0], acc[i][1], acc[i][2], acc[i][3]);
    }
}

// ---------------- per-node attention dots (layer 1) -------------------------
__global__ void k_al1(const float* __restrict__ a1s, const float* __restrict__ a1d) {
    int t = blockIdx.x * 256 + threadIdx.x;
    if (t >= NN * 4) return;
    int n = t >> 2, h = t & 3;
    const float* row = &g_h1f[(size_t)n * 128 + h * 32];
    float ss = 0.f, sd = 0.f;
#pragma unroll
    for (int c = 0; c < 32; c += 4) {
        float4 hv = *(const float4*)&row[c];
        float4 vs = *(const float4*)&a1s[h * 32 + c];
        float4 vd = *(const float4*)&a1d[h * 32 + c];
        ss += hv.x * vs.x + hv.y * vs.y + hv.z * vs.z + hv.w * vs.w;
        sd += hv.x * vd.x + hv.y * vd.y + hv.z * vd.z + hv.w * vd.w;
    }
    g_als1[t] = ss;
    g_ald1[t] = sd;
}

// ---------------- layer-1 edge logits + seg-max + edge_index output ---------
__global__ void k_e1(const int* __restrict__ src, const int* __restrict__ dst,
                     float* __restrict__ out_ei) {
    int e = blockIdx.x * 256 + threadIdx.x;
    if (e >= EPt) return;
    int s, d;
    float4 ae;
    if (e < EE) {
        s = src[e]; d = dst[e];
        ae = *(const float4*)&g_ae1[(size_t)e * 4];
    } else {
        s = d = e - EE;
        ae = *(const float4*)&g_slae1[(size_t)s * 4];
    }
    float4 as4 = *(const float4*)&g_als1[(size_t)s * 4];
    float4 ad4 = *(const float4*)&g_ald1[(size_t)d * 4];
    float4 v;
    v.x = lrelu(as4.x + ad4.x + ae.x);
    v.y = lrelu(as4.y + ad4.y + ae.y);
    v.z = lrelu(as4.z + ad4.z + ae.z);
    v.w = lrelu(as4.w + ad4.w + ae.w);
    *(float4*)&g_e1[(size_t)e * 4] = v;
    atomicMax(&g_m1[d * 4 + 0], fenc(v.x));
    atomicMax(&g_m1[d * 4 + 1], fenc(v.y));
    atomicMax(&g_m1[d * 4 + 2], fenc(v.z));
    atomicMax(&g_m1[d * 4 + 3], fenc(v.w));
    out_ei[e] = (float)s;
    out_ei[(size_t)EPt + e] = (float)d;
}

// ---------------- layer-1 exp + z + weighted feature scatter (warp/edge) ----
__global__ void k_p1(const int* __restrict__ src, const int* __restrict__ dst) {
    int warp = (blockIdx.x * 256 + threadIdx.x) >> 5;
    int lane = threadIdx.x & 31;
    if (warp >= EPt) return;
    int s, d;
    if (warp < EE) { s = src[warp]; d = dst[warp]; }
    else           { s = d = warp - EE; }
    float ph = 0.f;
    if (lane < 4) {
        float ev = g_e1[(size_t)warp * 4 + lane];
        float m = fdec(g_m1[d * 4 + lane]);
        ph = expf(ev - m);
        atomicAdd(&g_z1[d * 4 + lane], ph);
    }
    float p = __shfl_sync(0xffffffffu, ph, lane >> 3);
    float4 hv = *(const float4*)&g_h1f[(size_t)s * 128 + lane * 4];
    red_add_v4(&g_acc1[(size_t)d * 128 + lane * 4],
               make_float4(hv.x * p, hv.y * p, hv.z * p, hv.w * p));
}

// ---------------- layer-1 normalize + bias + elu (in place -> h1) -----------
__global__ void k_norm1(const float* __restrict__ b1) {
    int t = blockIdx.x * 256 + threadIdx.x;
    if (t >= NN * 32) return;
    int n = t >> 5, q = t & 31;
    int c4 = q * 4;
    float z = g_z1[n * 4 + (q >> 3)];
    float inv = 1.f / z;
    float4 a = *(float4*)&g_acc1[(size_t)n * 128 + c4];
    float4 bv = *(const float4*)&b1[c4];
    a.x = elu1(a.x * inv + bv.x);
    a.y = elu1(a.y * inv + bv.y);
    a.z = elu1(a.z * inv + bv.z);
    a.w = elu1(a.w * inv + bv.w);
    *(float4*)&g_acc1[(size_t)n * 128 + c4] = a;
}

// ---------------- GEMM2: h2f = h1 @ W2 (100000x128 @ 128x32) ----------------
__global__ void k_gemm2(const float* __restrict__ W2) {
    __shared__ float Ws[128 * 32];
    int tid = threadIdx.x;
    for (int i = tid; i < 128 * 32; i += 256) Ws[i] = W2[i];
    __syncthreads();
    int n = blockIdx.x * 32 + (tid >> 3);
    int c4 = (tid & 7) * 4;
    const float* hrow = &g_acc1[(size_t)n * 128];
    float4 acc = make_float4(0, 0, 0, 0);
#pragma unroll 8
    for (int k = 0; k < 128; k++) {
        float hv = __ldg(&hrow[k]);
        float4 w = *(float4*)&Ws[k * 32 + c4];
        acc.x += hv * w.x;
        acc.y += hv * w.y;
        acc.z += hv * w.z;
        acc.w += hv * w.w;
    }
    *(float4*)&g_h2f[(size_t)n * 32 + c4] = acc;
}

__global__ void k_al2(const float* __restrict__ a2s, const float* __restrict__ a2d) {
    int n = blockIdx.x * 256 + threadIdx.x;
    if (n >= NN) return;
    const float* row = &g_h2f[(size_t)n * 32];
    float ss = 0.f, sd = 0.f;
#pragma unroll
    for (int c = 0; c < 32; c += 4) {
        float4 hv = *(const float4*)&row[c];
        float4 vs = *(const float4*)&a2s[c];
        float4 vd = *(const float4*)&a2d[c];
        ss += hv.x * vs.x + hv.y * vs.y + hv.z * vs.z + hv.w * vs.w;
        sd += hv.x * vd.x + hv.y * vd.y + hv.z * vd.z + hv.w * vd.w;
    }
    g_als2[n] = ss;
    g_ald2[n] = sd;
}

// ---------------- layer-2 edge logits + seg-max ------------------------------
__global__ void k_e2(const int* __restrict__ src, const int* __restrict__ dst) {
    int e = blockIdx.x * 256 + threadIdx.x;
    if (e >= EPt) return;
    int s, d;
    float ae;
    if (e < EE) { s = src[e]; d = dst[e]; ae = g_ae2[e]; }
    else        { s = d = e - EE; ae = g_slae2[s]; }
    float v = lrelu(g_als2[s] + g_ald2[d] + ae);
    g_e2[e] = v;
    atomicMax(&g_m2[d], fenc(v));
}

// ---------------- layer-2 exp + z + scatter (8 lanes/edge) -------------------
__global__ void k_p2(const int* __restrict__ src, const int* __restrict__ dst) {
    int t = blockIdx.x * 256 + threadIdx.x;
    int e = t >> 3, sub = t & 7;
    if (e >= EPt) return;
    int s, d;
    if (e < EE) { s = src[e]; d = dst[e]; }
    else        { s = d = e - EE; }
    float p = expf(g_e2[e] - fdec(g_m2[d]));
    if (sub == 0) atomicAdd(&g_z2[d], p);
    float4 hv = *(const float4*)&g_h2f[(size_t)s * 32 + sub * 4];
    red_add_v4(&g_acc2[(size_t)d * 32 + sub * 4],
               make_float4(hv.x * p, hv.y * p, hv.z * p, hv.w * p));
}

// ---------------- layer-2 normalize + bias + elu -> output h2 ----------------
__global__ void k_out2(const float* __restrict__ b2, float* __restrict__ out_h2) {
    int t = blockIdx.x * 256 + threadIdx.x;
    if (t >= NN * 8) return;
    int n = t >> 3;
    int c4 = (t & 7) * 4;
    float inv = 1.f / g_z2[n];
    float4 a = *(float4*)&g_acc2[(size_t)n * 32 + c4];
    float4 bv = *(const float4*)&b2[c4];
    a.x = elu1(a.x * inv + bv.x);
    a.y = elu1(a.y * inv + bv.y);
    a.z = elu1(a.z * inv + bv.z);
    a.w = elu1(a.w * inv + bv.w);
    *(float4*)&out_h2[(size_t)n * 32 + c4] = a;
}

// ---------------- alpha2 output ----------------------------------------------
__global__ void k_alpha2(const int* __restrict__ dst, float* __restrict__ out_alpha) {
    int e = blockIdx.x * 256 + threadIdx.x;
    if (e >= EPt) return;
    int d = (e < EE) ? dst[e] : e - EE;
    float p = expf(g_e2[e] - fdec(g_m2[d]));
    out_alpha[e] = p / g_z2[d];
}

// ---------------- launcher ---------------------------------------------------
static inline int dgrid(long n, int b) { return (int)((n + b - 1) / b); }

extern "C" void kernel_launch(void* const* d_in, const int* in_sizes, int n_in,
                              void* d_out, int out_size) {
    const float* x     = (const float*)d_in[0];
    const int*   ei    = (const int*)d_in[1];
    const int*   src   = ei;
    const int*   dst   = ei + EE;
    const float* eattr = (const float*)d_in[2];
    const float* W1    = (const float*)d_in[3];
    const float* W1e   = (const float*)d_in[4];
    const float* a1s   = (const float*)d_in[5];
    const float* a1d   = (const float*)d_in[6];
    const float* a1e   = (const float*)d_in[7];
    const float* b1    = (const float*)d_in[8];
    const float* W2    = (const float*)d_in[9];
    const float* W2e   = (const float*)d_in[10];
    const float* a2s   = (const float*)d_in[11];
    const float* a2d   = (const float*)d_in[12];
    const float* a2e   = (const float*)d_in[13];
    const float* b2    = (const float*)d_in[14];

    float* out       = (float*)d_out;
    float* out_h2    = out;                                  // N*32
    float* out_ei    = out + (size_t)NN * CC;                // 2*EPt
    float* out_alpha = out_ei + 2 * (size_t)EPt;             // EPt

    // zero scratch that gets accumulated into (async memsets are capturable)
    void* p;
    cudaGetSymbolAddress(&p, g_deg);   cudaMemsetAsync(p, 0, (size_t)NN * 4);
    cudaGetSymbolAddress(&p, g_slae1); cudaMemsetAsync(p, 0, (size_t)NN * 16);
    cudaGetSymbolAddress(&p, g_slae2); cudaMemsetAsync(p, 0, (size_t)NN * 4);
    cudaGetSymbolAddress(&p, g_m1);    cudaMemsetAsync(p, 0, (size_t)NN * 16);
    cudaGetSymbolAddress(&p, g_z1);    cudaMemsetAsync(p, 0, (size_t)NN * 16);
    cudaGetSymbolAddress(&p, g_acc1);  cudaMemsetAsync(p, 0, (size_t)NN * 512);
    cudaGetSymbolAddress(&p, g_m2);    cudaMemsetAsync(p, 0, (size_t)NN * 4);
    cudaGetSymbolAddress(&p, g_z2);    cudaMemsetAsync(p, 0, (size_t)NN * 4);
    cudaGetSymbolAddress(&p, g_acc2);  cudaMemsetAsync(p, 0, (size_t)NN * 128);

    k_v<<<1, 128>>>(W1e, a1e, W2e, a2e);
    k_edge_pre<<<dgrid(EE, 256), 256>>>(eattr, dst);
    k_selfloop<<<dgrid(NN, 256), 256>>>();
    k_gemm1<<<dgrid(NN, 64), 256>>>(x, W1);
    k_al1<<<dgrid((long)NN * 4, 256), 256>>>(a1s, a1d);
    k_e1<<<dgrid(EPt, 256), 256>>>(src, dst, out_ei);
    k_p1<<<dgrid((long)EPt * 32, 256), 256>>>(src, dst);
    k_norm1<<<dgrid((long)NN * 32, 256), 256>>>(b1);
    k_gemm2<<<NN / 32, 256>>>(W2);
    k_al2<<<dgrid(NN, 256), 256>>>(a2s, a2d);
    k_e2<<<dgrid(EPt, 256), 256>>>(src, dst);
    k_p2<<<dgrid((long)EPt * 8, 256), 256>>>(src, dst);
    k_out2<<<dgrid((long)NN * 8, 256), 256>>>(b2, out_h2);
    k_alpha2<<<dgrid(EPt, 256), 256>>>(dst, out_alpha);
}

// round 3
// speedup vs baseline: 1.6183x; 1.6183x over previous
#include <cuda_runtime.h>

#define NN 100000
#define EE 1600000
#define EPt 1700000     // EE + NN (with self loops)
#define HC 128          // H*C layer1
#define CC 32
#define EDIM 16

// ---------------- scratch (static device allocations) -----------------------
__device__ __align__(16) float g_v1e[EDIM * 4];
__device__ __align__(16) float g_v2e[EDIM];
__device__            int      g_cnt[NN];
__device__            int      g_cnt2[NN];
__device__            int      g_rs[NN + 1];         // CSR row starts (by dst)
__device__            int      g_csrc[EE];           // CSR src ids
__device__            int      g_ceid[EE];           // CSR original edge ids
__device__ __align__(16) float g_ae1[(size_t)EE * 4];
__device__            float    g_ae2[EE];
__device__ __align__(16) float g_h1f[(size_t)NN * HC];
__device__ __align__(16) float g_als1[NN * 4];
__device__ __align__(16) float g_ald1[NN * 4];
__device__ __align__(16) float g_h1[(size_t)NN * HC];   // post-softmax/ELU h1
__device__ __align__(16) float g_h2f[(size_t)NN * CC];
__device__            float    g_als2[NN];
__device__            float    g_ald2[NN];
__device__            float    g_p2[EPt];
__device__            float    g_z2[NN];

// ---------------- helpers ---------------------------------------------------
__device__ __forceinline__ float lrelu(float x) { return x > 0.f ? x : 0.2f * x; }
__device__ __forceinline__ float elu1(float x)  { return x > 0.f ? x : expm1f(x); }

// ---------------- tiny precompute: v1e, v2e ---------------------------------
__global__ void k_v(const float* __restrict__ W1e, const float* __restrict__ a1e,
                    const float* __restrict__ W2e, const float* __restrict__ a2e) {
    int t = threadIdx.x;
    if (t < 64) {
        int d = t >> 2, h = t & 3;
        float s = 0.f;
        for (int c = 0; c < 32; c++) s += W1e[d * 128 + h * 32 + c] * a1e[h * 32 + c];
        g_v1e[d * 4 + h] = s;
    } else if (t < 80) {
        int d = t - 64;
        float s = 0.f;
        for (int c = 0; c < 32; c++) s += W2e[d * 32 + c] * a2e[c];
        g_v2e[d] = s;
    }
}

// ---------------- P0: edge-attr logits + degree count + edge_index output ---
__global__ void k_pre(const float* __restrict__ eattr,
                      const int* __restrict__ src, const int* __restrict__ dst,
                      float* __restrict__ out_ei) {
    int e = blockIdx.x * 256 + threadIdx.x;
    if (e >= EPt) return;
    if (e >= EE) {
        float n = (float)(e - EE);
        out_ei[e] = n;
        out_ei[(size_t)EPt + e] = n;
        return;
    }
    float w[16];
    const float4* ep = (const float4*)(eattr + (size_t)e * EDIM);
    *(float4*)&w[0]  = ep[0];
    *(float4*)&w[4]  = ep[1];
    *(float4*)&w[8]  = ep[2];
    *(float4*)&w[12] = ep[3];
    float a0 = 0, a1 = 0, a2 = 0, a3 = 0, b = 0;
#pragma unroll
    for (int j = 0; j < 16; j++) {
        float wv = w[j];
        a0 += wv * g_v1e[j * 4 + 0];
        a1 += wv * g_v1e[j * 4 + 1];
        a2 += wv * g_v1e[j * 4 + 2];
        a3 += wv * g_v1e[j * 4 + 3];
        b  += wv * g_v2e[j];
    }
    *(float4*)&g_ae1[(size_t)e * 4] = make_float4(a0, a1, a2, a3);
    g_ae2[e] = b;
    int s = src[e], d = dst[e];
    atomicAdd(&g_cnt[d], 1);
    out_ei[e] = (float)s;
    out_ei[(size_t)EPt + e] = (float)d;
}

// ---------------- exclusive scan over counts (single block) ------------------
__global__ void k_scan() {
    __shared__ int sh[1024];
    const int CH = (NN + 1023) / 1024;
    int t = threadIdx.x;
    int beg = t * CH, end = min(beg + CH, NN);
    int s = 0;
    for (int i = beg; i < end; i++) s += g_cnt[i];
    sh[t] = s;
    __syncthreads();
    for (int off = 1; off < 1024; off <<= 1) {
        int v = 0;
        if (t >= off) v = sh[t - off];
        __syncthreads();
        sh[t] += v;
        __syncthreads();
    }
    int run = (t == 0) ? 0 : sh[t - 1];
    for (int i = beg; i < end; i++) { g_rs[i] = run; run += g_cnt[i]; }
    if (t == 1023) g_rs[NN] = sh[1023];
}

// ---------------- CSR fill ---------------------------------------------------
__global__ void k_fill(const int* __restrict__ src, const int* __restrict__ dst) {
    int e = blockIdx.x * 256 + threadIdx.x;
    if (e >= EE) return;
    int d = dst[e];
    int pos = g_rs[d] + atomicAdd(&g_cnt2[d], 1);
    g_csrc[pos] = src[e];
    g_ceid[pos] = e;
}

// ---------------- GEMM1: h1f = x @ W1 (100000x128 @ 128x128) ----------------
// 128x128 block tile, 8x8 per thread, BK=8
__global__ void __launch_bounds__(256) k_gemm1(const float* __restrict__ X,
                                               const float* __restrict__ W) {
    __shared__ float As[8][128];
    __shared__ float Bs[8][128];
    int tid = threadIdx.x;
    int row0 = blockIdx.x * 128;
    int tm = tid >> 4, tn = tid & 15;
    float acc[8][8];
#pragma unroll
    for (int i = 0; i < 8; i++)
#pragma unroll
        for (int j = 0; j < 8; j++) acc[i][j] = 0.f;

    int lr = tid >> 1;          // row within tile 0..127
    int lk = (tid & 1) * 4;     // k offset
    int wr = tid >> 5;          // k row for W
    int wc = (tid & 31) * 4;    // col

    for (int k0 = 0; k0 < 128; k0 += 8) {
        int gr = row0 + lr;
        float4 av = (gr < NN) ? *(const float4*)&X[(size_t)gr * 128 + k0 + lk]
                              : make_float4(0, 0, 0, 0);
        As[lk + 0][lr] = av.x;
        As[lk + 1][lr] = av.y;
        As[lk + 2][lr] = av.z;
        As[lk + 3][lr] = av.w;
        *(float4*)&Bs[wr][wc] = *(const float4*)&W[(size_t)(k0 + wr) * 128 + wc];
        __syncthreads();
#pragma unroll
        for (int kk = 0; kk < 8; kk++) {
            float a[8], b[8];
            *(float4*)&a[0] = *(float4*)&As[kk][tm * 8];
            *(float4*)&a[4] = *(float4*)&As[kk][tm * 8 + 4];
            *(float4*)&b[0] = *(float4*)&Bs[kk][tn * 8];
            *(float4*)&b[4] = *(float4*)&Bs[kk][tn * 8 + 4];
#pragma unroll
            for (int i = 0; i < 8; i++)
#pragma unroll
                for (int j = 0; j < 8; j++) acc[i][j] += a[i] * b[j];
        }
        __syncthreads();
    }
#pragma unroll
    for (int i = 0; i < 8; i++) {
        int row = row0 + tm * 8 + i;
        if (row < NN) {
            *(float4*)&g_h1f[(size_t)row * 128 + tn * 8]     = *(float4*)&acc[i][0];
            *(float4*)&g_h1f[(size_t)row * 128 + tn * 8 + 4] = *(float4*)&acc[i][4];
        }
    }
}

// ---------------- per-node attention dots (layer 1) -------------------------
__global__ void k_al1(const float* __restrict__ a1s, const float* __restrict__ a1d) {
    int t = blockIdx.x * 256 + threadIdx.x;
    if (t >= NN * 4) return;
    int n = t >> 2, h = t & 3;
    const float* row = &g_h1f[(size_t)n * 128 + h * 32];
    float ss = 0.f, sd = 0.f;
#pragma unroll
    for (int c = 0; c < 32; c += 4) {
        float4 hv = *(const float4*)&row[c];
        float4 vs = *(const float4*)&a1s[h * 32 + c];
        float4 vd = *(const float4*)&a1d[h * 32 + c];
        ss += hv.x * vs.x + hv.y * vs.y + hv.z * vs.z + hv.w * vs.w;
        sd += hv.x * vd.x + hv.y * vd.y + hv.z * vd.z + hv.w * vd.w;
    }
    g_als1[t] = ss;
    g_ald1[t] = sd;
}

// ---------------- layer-1 fused softmax gather (warp per node) ---------------
__global__ void __launch_bounds__(256) k_gather1(const float* __restrict__ b1) {
    int n = (blockIdx.x * 256 + threadIdx.x) >> 5;
    int lane = threadIdx.x & 31;
    if (n >= NN) return;
    int beg = g_rs[n], end = g_rs[n + 1];
    int deg = end - beg;
    int head = lane >> 3;
    float ald_h  = g_ald1[n * 4 + head];
    float alsn_h = g_als1[n * 4 + head];
    float4 acc = make_float4(0, 0, 0, 0);
    float z = 0.f, sumae = 0.f;

    for (int base = beg; base < end; base += 32) {
        int m = min(32, end - base);
        int sl = 0, el = 0;
        if (lane < m) { sl = g_csrc[base + lane]; el = g_ceid[base + lane]; }
        for (int j = 0; j < m; j++) {
            int s   = __shfl_sync(0xffffffffu, sl, j);
            int eid = __shfl_sync(0xffffffffu, el, j);
            float ae  = __ldg(&g_ae1[(size_t)eid * 4 + head]);
            float als = __ldg(&g_als1[s * 4 + head]);
            float p = expf(lrelu(als + ald_h + ae));
            z += p;
            sumae += ae;
            float4 hv = *(const float4*)&g_h1f[(size_t)s * 128 + lane * 4];
            acc.x += p * hv.x; acc.y += p * hv.y;
            acc.z += p * hv.z; acc.w += p * hv.w;
        }
    }
    // self loop: attr = mean of incoming edge attrs (projected)
    float slae = sumae / fmaxf((float)deg, 1.f);
    float ps = expf(lrelu(alsn_h + ald_h + slae));
    z += ps;
    float4 hv = *(const float4*)&g_h1f[(size_t)n * 128 + lane * 4];
    acc.x += ps * hv.x; acc.y += ps * hv.y;
    acc.z += ps * hv.z; acc.w += ps * hv.w;

    float inv = 1.f / z;
    float4 bv = *(const float4*)&b1[lane * 4];
    float4 o;
    o.x = elu1(acc.x * inv + bv.x);
    o.y = elu1(acc.y * inv + bv.y);
    o.z = elu1(acc.z * inv + bv.z);
    o.w = elu1(acc.w * inv + bv.w);
    *(float4*)&g_h1[(size_t)n * 128 + lane * 4] = o;
}

// ---------------- GEMM2: h2f = h1 @ W2 (100000x128 @ 128x32) ----------------
__global__ void k_gemm2(const float* __restrict__ W2) {
    __shared__ float Ws[128 * 32];
    int tid = threadIdx.x;
    for (int i = tid; i < 128 * 32; i += 256) Ws[i] = W2[i];
    __syncthreads();
    int n = blockIdx.x * 32 + (tid >> 3);
    int c4 = (tid & 7) * 4;
    const float* hrow = &g_h1[(size_t)n * 128];
    float4 acc = make_float4(0, 0, 0, 0);
#pragma unroll 8
    for (int k = 0; k < 128; k++) {
        float hv = __ldg(&hrow[k]);
        float4 w = *(float4*)&Ws[k * 32 + c4];
        acc.x += hv * w.x;
        acc.y += hv * w.y;
        acc.z += hv * w.z;
        acc.w += hv * w.w;
    }
    *(float4*)&g_h2f[(size_t)n * 32 + c4] = acc;
}

__global__ void k_al2(const float* __restrict__ a2s, const float* __restrict__ a2d) {
    int n = blockIdx.x * 256 + threadIdx.x;
    if (n >= NN) return;
    const float* row = &g_h2f[(size_t)n * 32];
    float ss = 0.f, sd = 0.f;
#pragma unroll
    for (int c = 0; c < 32; c += 4) {
        float4 hv = *(const float4*)&row[c];
        float4 vs = *(const float4*)&a2s[c];
        float4 vd = *(const float4*)&a2d[c];
        ss += hv.x * vs.x + hv.y * vs.y + hv.z * vs.z + hv.w * vs.w;
        sd += hv.x * vd.x + hv.y * vd.y + hv.z * vd.z + hv.w * vd.w;
    }
    g_als2[n] = ss;
    g_ald2[n] = sd;
}

// ---------------- layer-2 fused softmax gather (warp per node) ---------------
__global__ void __launch_bounds__(256) k_gather2(const float* __restrict__ b2,
                                                 float* __restrict__ out_h2) {
    int n = (blockIdx.x * 256 + threadIdx.x) >> 5;
    int lane = threadIdx.x & 31;
    if (n >= NN) return;
    int beg = g_rs[n], end = g_rs[n + 1];
    int deg = end - beg;
    float ald  = g_ald2[n];
    float alsn = g_als2[n];
    float acc = 0.f, z = 0.f, sumae = 0.f;

    for (int base = beg; base < end; base += 32) {
        int m = min(32, end - base);
        int sl = 0, el = 0;
        if (lane < m) { sl = g_csrc[base + lane]; el = g_ceid[base + lane]; }
        for (int j = 0; j < m; j++) {
            int s   = __shfl_sync(0xffffffffu, sl, j);
            int eid = __shfl_sync(0xffffffffu, el, j);
            float ae  = __ldg(&g_ae2[eid]);
            float als = __ldg(&g_als2[s]);
            float p = expf(lrelu(als + ald + ae));
            z += p;
            sumae += ae;
            if (lane == 0) g_p2[eid] = p;
            acc += p * __ldg(&g_h2f[(size_t)s * 32 + lane]);
        }
    }
    float slae = sumae / fmaxf((float)deg, 1.f);
    float ps = expf(lrelu(alsn + ald + slae));
    z += ps;
    acc += ps * g_h2f[(size_t)n * 32 + lane];
    if (lane == 0) { g_p2[EE + n] = ps; g_z2[n] = z; }
    out_h2[(size_t)n * 32 + lane] = elu1(acc / z + b2[lane]);
}

// ---------------- alpha2 output ----------------------------------------------
__global__ void k_alpha2(const int* __restrict__ dst, float* __restrict__ out_alpha) {
    int e = blockIdx.x * 256 + threadIdx.x;
    if (e >= EPt) return;
    int d = (e < EE) ? dst[e] : e - EE;
    out_alpha[e] = g_p2[e] / g_z2[d];
}

// ---------------- launcher ---------------------------------------------------
static inline int dgrid(long n, int b) { return (int)((n + b - 1) / b); }

extern "C" void kernel_launch(void* const* d_in, const int* in_sizes, int n_in,
                              void* d_out, int out_size) {
    const float* x     = (const float*)d_in[0];
    const int*   ei    = (const int*)d_in[1];
    const int*   src   = ei;
    const int*   dst   = ei + EE;
    const float* eattr = (const float*)d_in[2];
    const float* W1    = (const float*)d_in[3];
    const float* W1e   = (const float*)d_in[4];
    const float* a1s   = (const float*)d_in[5];
    const float* a1d   = (const float*)d_in[6];
    const float* a1e   = (const float*)d_in[7];
    const float* b1    = (const float*)d_in[8];
    const float* W2    = (const float*)d_in[9];
    const float* W2e   = (const float*)d_in[10];
    const float* a2s   = (const float*)d_in[11];
    const float* a2d   = (const float*)d_in[12];
    const float* a2e   = (const float*)d_in[13];
    const float* b2    = (const float*)d_in[14];

    float* out       = (float*)d_out;
    float* out_h2    = out;                                  // N*32
    float* out_ei    = out + (size_t)NN * CC;                // 2*EPt
    float* out_alpha = out_ei + 2 * (size_t)EPt;             // EPt

    void* p;
    cudaGetSymbolAddress(&p, g_cnt);  cudaMemsetAsync(p, 0, (size_t)NN * 4);
    cudaGetSymbolAddress(&p, g_cnt2); cudaMemsetAsync(p, 0, (size_t)NN * 4);

    k_v<<<1, 128>>>(W1e, a1e, W2e, a2e);
    k_pre<<<dgrid(EPt, 256), 256>>>(eattr, src, dst, out_ei);
    k_scan<<<1, 1024>>>();
    k_fill<<<dgrid(EE, 256), 256>>>(src, dst);
    k_gemm1<<<dgrid(NN, 128), 256>>>(x, W1);
    k_al1<<<dgrid((long)NN * 4, 256), 256>>>(a1s, a1d);
    k_gather1<<<dgrid((long)NN * 32, 256), 256>>>(b1);
    k_gemm2<<<NN / 32, 256>>>(W2);
    k_al2<<<dgrid(NN, 256), 256>>>(a2s, a2d);
    k_gather2<<<dgrid((long)NN * 32, 256), 256>>>(b2, out_h2);
    k_alpha2<<<dgrid(EPt, 256), 256>>>(dst, out_alpha);
}

// round 4
// speedup vs baseline: 1.8033x; 1.1143x over previous
#include <cuda_runtime.h>

#define NN 100000
#define EE 1600000
#define EPt 1700000     // EE + NN (with self loops)
#define HC 128          // H*C layer1
#define CC 32
#define EDIM 16
#define FULL 0xffffffffu

// ---------------- scratch (static device allocations) -----------------------
__device__ __align__(16) float g_v1e[EDIM * 4];
__device__ __align__(16) float g_v2e[EDIM];
__device__            int      g_cnt[NN];
__device__            int      g_cnt2[NN];
__device__            int      g_rs[NN + 1];         // CSR row starts (by dst)
__device__            int      g_csrc[EE];           // CSR src ids
__device__            int      g_ceid[EE];           // CSR original edge ids
__device__ __align__(16) float g_ae1[(size_t)EE * 4];
__device__            float    g_ae2[EE];
__device__ __align__(16) float g_h1f[(size_t)NN * HC];
__device__ __align__(16) float g_als1[NN * 4];
__device__ __align__(16) float g_ald1[NN * 4];
__device__ __align__(16) float g_h1[(size_t)NN * HC];   // post-softmax/ELU h1
__device__ __align__(16) float g_h2f[(size_t)NN * CC];
__device__            float    g_als2[NN];
__device__            float    g_ald2[NN];
__device__            float    g_p2[EPt];
__device__            float    g_z2[NN];

// ---------------- helpers ---------------------------------------------------
__device__ __forceinline__ float lrelu(float x) { return x > 0.f ? x : 0.2f * x; }
__device__ __forceinline__ float elu1(float x)  { return x > 0.f ? x : expm1f(x); }

// ---------------- tiny precompute: v1e, v2e ---------------------------------
__global__ void k_v(const float* __restrict__ W1e, const float* __restrict__ a1e,
                    const float* __restrict__ W2e, const float* __restrict__ a2e) {
    int t = threadIdx.x;
    if (t < 64) {
        int d = t >> 2, h = t & 3;
        float s = 0.f;
        for (int c = 0; c < 32; c++) s += W1e[d * 128 + h * 32 + c] * a1e[h * 32 + c];
        g_v1e[d * 4 + h] = s;
    } else if (t < 80) {
        int d = t - 64;
        float s = 0.f;
        for (int c = 0; c < 32; c++) s += W2e[d * 32 + c] * a2e[c];
        g_v2e[d] = s;
    }
}

// ---------------- P0: edge-attr logits + degree count + edge_index output ---
__global__ void k_pre(const float* __restrict__ eattr,
                      const int* __restrict__ src, const int* __restrict__ dst,
                      float* __restrict__ out_ei) {
    int e = blockIdx.x * 256 + threadIdx.x;
    if (e >= EPt) return;
    if (e >= EE) {
        float n = (float)(e - EE);
        out_ei[e] = n;
        out_ei[(size_t)EPt + e] = n;
        return;
    }
    float w[16];
    const float4* ep = (const float4*)(eattr + (size_t)e * EDIM);
    *(float4*)&w[0]  = ep[0];
    *(float4*)&w[4]  = ep[1];
    *(float4*)&w[8]  = ep[2];
    *(float4*)&w[12] = ep[3];
    float a0 = 0, a1 = 0, a2 = 0, a3 = 0, b = 0;
#pragma unroll
    for (int j = 0; j < 16; j++) {
        float wv = w[j];
        a0 += wv * g_v1e[j * 4 + 0];
        a1 += wv * g_v1e[j * 4 + 1];
        a2 += wv * g_v1e[j * 4 + 2];
        a3 += wv * g_v1e[j * 4 + 3];
        b  += wv * g_v2e[j];
    }
    *(float4*)&g_ae1[(size_t)e * 4] = make_float4(a0, a1, a2, a3);
    g_ae2[e] = b;
    int s = src[e], d = dst[e];
    atomicAdd(&g_cnt[d], 1);
    out_ei[e] = (float)s;
    out_ei[(size_t)EPt + e] = (float)d;
}

// ---------------- exclusive scan over counts (single block) ------------------
__global__ void k_scan() {
    __shared__ int sh[1024];
    const int CH = (NN + 1023) / 1024;
    int t = threadIdx.x;
    int beg = t * CH, end = min(beg + CH, NN);
    int s = 0;
    for (int i = beg; i < end; i++) s += g_cnt[i];
    sh[t] = s;
    __syncthreads();
    for (int off = 1; off < 1024; off <<= 1) {
        int v = 0;
        if (t >= off) v = sh[t - off];
        __syncthreads();
        sh[t] += v;
        __syncthreads();
    }
    int run = (t == 0) ? 0 : sh[t - 1];
    for (int i = beg; i < end; i++) { g_rs[i] = run; run += g_cnt[i]; }
    if (t == 1023) g_rs[NN] = sh[1023];
}

// ---------------- CSR fill ---------------------------------------------------
__global__ void k_fill(const int* __restrict__ src, const int* __restrict__ dst) {
    int e = blockIdx.x * 256 + threadIdx.x;
    if (e >= EE) return;
    int d = dst[e];
    int pos = g_rs[d] + atomicAdd(&g_cnt2[d], 1);
    g_csrc[pos] = src[e];
    g_ceid[pos] = e;
}

// ---------------- GEMM1: h1f = x @ W1 (100000x128 @ 128x128) ----------------
__global__ void __launch_bounds__(256) k_gemm1(const float* __restrict__ X,
                                               const float* __restrict__ W) {
    __shared__ float As[8][128];
    __shared__ float Bs[8][128];
    int tid = threadIdx.x;
    int row0 = blockIdx.x * 128;
    int tm = tid >> 4, tn = tid & 15;
    float acc[8][8];
#pragma unroll
    for (int i = 0; i < 8; i++)
#pragma unroll
        for (int j = 0; j < 8; j++) acc[i][j] = 0.f;

    int lr = tid >> 1;
    int lk = (tid & 1) * 4;
    int wr = tid >> 5;
    int wc = (tid & 31) * 4;

    for (int k0 = 0; k0 < 128; k0 += 8) {
        int gr = row0 + lr;
        float4 av = (gr < NN) ? *(const float4*)&X[(size_t)gr * 128 + k0 + lk]
                              : make_float4(0, 0, 0, 0);
        As[lk + 0][lr] = av.x;
        As[lk + 1][lr] = av.y;
        As[lk + 2][lr] = av.z;
        As[lk + 3][lr] = av.w;
        *(float4*)&Bs[wr][wc] = *(const float4*)&W[(size_t)(k0 + wr) * 128 + wc];
        __syncthreads();
#pragma unroll
        for (int kk = 0; kk < 8; kk++) {
            float a[8], b[8];
            *(float4*)&a[0] = *(float4*)&As[kk][tm * 8];
            *(float4*)&a[4] = *(float4*)&As[kk][tm * 8 + 4];
            *(float4*)&b[0] = *(float4*)&Bs[kk][tn * 8];
            *(float4*)&b[4] = *(float4*)&Bs[kk][tn * 8 + 4];
#pragma unroll
            for (int i = 0; i < 8; i++)
#pragma unroll
                for (int j = 0; j < 8; j++) acc[i][j] += a[i] * b[j];
        }
        __syncthreads();
    }
#pragma unroll
    for (int i = 0; i < 8; i++) {
        int row = row0 + tm * 8 + i;
        if (row < NN) {
            *(float4*)&g_h1f[(size_t)row * 128 + tn * 8]     = *(float4*)&acc[i][0];
            *(float4*)&g_h1f[(size_t)row * 128 + tn * 8 + 4] = *(float4*)&acc[i][4];
        }
    }
}

// ---------------- per-node attention dots (layer 1) -------------------------
__global__ void k_al1(const float* __restrict__ a1s, const float* __restrict__ a1d) {
    int t = blockIdx.x * 256 + threadIdx.x;
    if (t >= NN * 4) return;
    int n = t >> 2, h = t & 3;
    const float* row = &g_h1f[(size_t)n * 128 + h * 32];
    float ss = 0.f, sd = 0.f;
#pragma unroll
    for (int c = 0; c < 32; c += 4) {
        float4 hv = *(const float4*)&row[c];
        float4 vs = *(const float4*)&a1s[h * 32 + c];
        float4 vd = *(const float4*)&a1d[h * 32 + c];
        ss += hv.x * vs.x + hv.y * vs.y + hv.z * vs.z + hv.w * vs.w;
        sd += hv.x * vd.x + hv.y * vd.y + hv.z * vd.z + hv.w * vd.w;
    }
    g_als1[t] = ss;
    g_ald1[t] = sd;
}

// ---------------- layer-1 fused softmax gather (warp per node) ---------------
// Chunks of 8 edges; lane (e*4+h) computes exp once per (edge,head) pair.
__global__ void __launch_bounds__(256) k_gather1(const float* __restrict__ b1) {
    int n = (blockIdx.x * 256 + threadIdx.x) >> 5;
    int lane = threadIdx.x & 31;
    if (n >= NN) return;
    int beg = g_rs[n], end = g_rs[n + 1];
    int deg = end - beg;
    int head = lane >> 3;      // head for feature accumulation (8 lanes each)
    int lh = lane & 3;         // head for exp computation
    int le = lane >> 2;        // edge slot 0..7 for exp computation
    float ald_lh = g_ald1[n * 4 + lh];
    float4 acc = make_float4(0, 0, 0, 0);
    float z = 0.f, sumae_l = 0.f;

    for (int base = beg; base < end; base += 8) {
        int m = end - base; if (m > 8) m = 8;
        int sl = 0;
        float p = 0.f;
        if (le < m) {
            sl = g_csrc[base + le];
            int el = g_ceid[base + le];
            float ae = __ldg(&g_ae1[(size_t)el * 4 + lh]);
            float als = __ldg(&g_als1[sl * 4 + lh]);
            p = __expf(lrelu(als + ald_lh + ae));
            sumae_l += ae;
        }
        if (m == 8) {
#pragma unroll
            for (int j = 0; j < 8; j++) {
                int s = __shfl_sync(FULL, sl, j * 4);
                float pj = __shfl_sync(FULL, p, j * 4 + head);
                z += pj;
                float4 hv = *(const float4*)&g_h1f[(size_t)s * 128 + lane * 4];
                acc.x += pj * hv.x; acc.y += pj * hv.y;
                acc.z += pj * hv.z; acc.w += pj * hv.w;
            }
        } else {
            for (int j = 0; j < m; j++) {
                int s = __shfl_sync(FULL, sl, j * 4);
                float pj = __shfl_sync(FULL, p, j * 4 + head);
                z += pj;
                float4 hv = *(const float4*)&g_h1f[(size_t)s * 128 + lane * 4];
                acc.x += pj * hv.x; acc.y += pj * hv.y;
                acc.z += pj * hv.z; acc.w += pj * hv.w;
            }
        }
    }
    // reduce sumae over edge-slot lanes (same lh)
    sumae_l += __shfl_xor_sync(FULL, sumae_l, 4);
    sumae_l += __shfl_xor_sync(FULL, sumae_l, 8);
    sumae_l += __shfl_xor_sync(FULL, sumae_l, 16);
    float sumae = __shfl_sync(FULL, sumae_l, head);   // lane h holds head h's sum

    float alsn = g_als1[n * 4 + head];
    float ald_h = g_ald1[n * 4 + head];
    float slae = sumae / fmaxf((float)deg, 1.f);
    float ps = __expf(lrelu(alsn + ald_h + slae));
    z += ps;
    float4 hv = *(const float4*)&g_h1f[(size_t)n * 128 + lane * 4];
    acc.x += ps * hv.x; acc.y += ps * hv.y;
    acc.z += ps * hv.z; acc.w += ps * hv.w;

    float inv = 1.f / z;
    float4 bv = *(const float4*)&b1[lane * 4];
    float4 o;
    o.x = elu1(acc.x * inv + bv.x);
    o.y = elu1(acc.y * inv + bv.y);
    o.z = elu1(acc.z * inv + bv.z);
    o.w = elu1(acc.w * inv + bv.w);
    *(float4*)&g_h1[(size_t)n * 128 + lane * 4] = o;
}

// ---------------- GEMM2 + fused attention dots (layer 2) --------------------
__global__ void k_gemm2(const float* __restrict__ W2,
                        const float* __restrict__ a2s, const float* __restrict__ a2d) {
    __shared__ float Ws[128 * 32];
    int tid = threadIdx.x;
    for (int i = tid; i < 128 * 32; i += 256) Ws[i] = W2[i];
    __syncthreads();
    int n = blockIdx.x * 32 + (tid >> 3);
    int c4 = (tid & 7) * 4;
    const float* hrow = &g_h1[(size_t)n * 128];
    float4 acc = make_float4(0, 0, 0, 0);
#pragma unroll 8
    for (int k = 0; k < 128; k++) {
        float hv = __ldg(&hrow[k]);
        float4 w = *(float4*)&Ws[k * 32 + c4];
        acc.x += hv * w.x;
        acc.y += hv * w.y;
        acc.z += hv * w.z;
        acc.w += hv * w.w;
    }
    *(float4*)&g_h2f[(size_t)n * 32 + c4] = acc;
    // fused per-node dots with a2_src / a2_dst
    float4 vs = *(const float4*)&a2s[c4];
    float4 vd = *(const float4*)&a2d[c4];
    float ss = acc.x * vs.x + acc.y * vs.y + acc.z * vs.z + acc.w * vs.w;
    float sd = acc.x * vd.x + acc.y * vd.y + acc.z * vd.z + acc.w * vd.w;
#pragma unroll
    for (int off = 1; off < 8; off <<= 1) {
        ss += __shfl_xor_sync(FULL, ss, off);
        sd += __shfl_xor_sync(FULL, sd, off);
    }
    if ((tid & 7) == 0) { g_als2[n] = ss; g_ald2[n] = sd; }
}

// ---------------- layer-2 fused softmax gather (warp per node) ---------------
// Chunks of 32; each lane computes its own edge's exp once.
__global__ void __launch_bounds__(256) k_gather2(const float* __restrict__ b2,
                                                 float* __restrict__ out_h2) {
    int n = (blockIdx.x * 256 + threadIdx.x) >> 5;
    int lane = threadIdx.x & 31;
    if (n >= NN) return;
    int beg = g_rs[n], end = g_rs[n + 1];
    int deg = end - beg;
    float ald  = g_ald2[n];
    float alsn = g_als2[n];
    float acc = 0.f, z = 0.f, sumae = 0.f;

    for (int base = beg; base < end; base += 32) {
        int m = end - base; if (m > 32) m = 32;
        int sl = 0;
        float p = 0.f;
        if (lane < m) {
            sl = g_csrc[base + lane];
            int el = g_ceid[base + lane];
            float ae = __ldg(&g_ae2[el]);
            float als = __ldg(&g_als2[sl]);
            p = __expf(lrelu(als + ald + ae));
            sumae += ae;
            g_p2[el] = p;
        }
        for (int j = 0; j < m; j++) {
            int s = __shfl_sync(FULL, sl, j);
            float pj = __shfl_sync(FULL, p, j);
            z += pj;
            acc += pj * __ldg(&g_h2f[(size_t)s * 32 + lane]);
        }
    }
    // total sumae across lanes
#pragma unroll
    for (int off = 16; off; off >>= 1) sumae += __shfl_xor_sync(FULL, sumae, off);

    float slae = sumae / fmaxf((float)deg, 1.f);
    float ps = __expf(lrelu(alsn + ald + slae));
    z += ps;
    acc += ps * g_h2f[(size_t)n * 32 + lane];
    if (lane == 0) { g_p2[EE + n] = ps; g_z2[n] = z; }
    out_h2[(size_t)n * 32 + lane] = elu1(acc / z + b2[lane]);
}

// ---------------- alpha2 output ----------------------------------------------
__global__ void k_alpha2(const int* __restrict__ dst, float* __restrict__ out_alpha) {
    int e = blockIdx.x * 256 + threadIdx.x;
    if (e >= EPt) return;
    int d = (e < EE) ? dst[e] : e - EE;
    out_alpha[e] = g_p2[e] / g_z2[d];
}

// ---------------- launcher ---------------------------------------------------
static inline int dgrid(long n, int b) { return (int)((n + b - 1) / b); }

extern "C" void kernel_launch(void* const* d_in, const int* in_sizes, int n_in,
                              void* d_out, int out_size) {
    const float* x     = (const float*)d_in[0];
    const int*   ei    = (const int*)d_in[1];
    const int*   src   = ei;
    const int*   dst   = ei + EE;
    const float* eattr = (const float*)d_in[2];
    const float* W1    = (const float*)d_in[3];
    const float* W1e   = (const float*)d_in[4];
    const float* a1s   = (const float*)d_in[5];
    const float* a1d   = (const float*)d_in[6];
    const float* a1e   = (const float*)d_in[7];
    const float* b1    = (const float*)d_in[8];
    const float* W2    = (const float*)d_in[9];
    const float* W2e   = (const float*)d_in[10];
    const float* a2s   = (const float*)d_in[11];
    const float* a2d   = (const float*)d_in[12];
    const float* a2e   = (const float*)d_in[13];
    const float* b2    = (const float*)d_in[14];

    float* out       = (float*)d_out;
    float* out_h2    = out;                                  // N*32
    float* out_ei    = out + (size_t)NN * CC;                // 2*EPt
    float* out_alpha = out_ei + 2 * (size_t)EPt;             // EPt

    void* p;
    cudaGetSymbolAddress(&p, g_cnt);  cudaMemsetAsync(p, 0, (size_t)NN * 4);
    cudaGetSymbolAddress(&p, g_cnt2); cudaMemsetAsync(p, 0, (size_t)NN * 4);

    k_v<<<1, 128>>>(W1e, a1e, W2e, a2e);
    k_pre<<<dgrid(EPt, 256), 256>>>(eattr, src, dst, out_ei);
    k_scan<<<1, 1024>>>();
    k_fill<<<dgrid(EE, 256), 256>>>(src, dst);
    k_gemm1<<<dgrid(NN, 128), 256>>>(x, W1);
    k_al1<<<dgrid((long)NN * 4, 256), 256>>>(a1s, a1d);
    k_gather1<<<dgrid((long)NN * 32, 256), 256>>>(b1);
    k_gemm2<<<NN / 32, 256>>>(W2, a2s, a2d);
    k_gather2<<<dgrid((long)NN * 32, 256), 256>>>(b2, out_h2);
    k_alpha2<<<dgrid(EPt, 256), 256>>>(dst, out_alpha);
}

// round 7
// speedup vs baseline: 1.9107x; 1.0596x over previous
#include <cuda_runtime.h>
#include <cuda_bf16.h>

#define NN 100000
#define EE 1600000
#define EPt 1700000     // EE + NN (with self loops)
#define HC 128          // H*C layer1
#define CC 32
#define EDIM 16
#define FULL 0xffffffffu

// ---------------- scratch (static device allocations) -----------------------
__device__            int           g_cnt[2 * NN];           // [0,NN)=count, [NN,2NN)=fill cursor
__device__            int           g_rs[NN + 1];            // CSR row starts (by dst)
__device__            int           g_csrc[EE];              // CSR src ids
__device__            int           g_ceid[EE];              // CSR original edge ids
__device__ __align__(16) float      g_ae1[(size_t)EE * 4];
__device__            float         g_ae2[EE];
__device__ __align__(16) __nv_bfloat16 g_h1b[(size_t)NN * HC];  // bf16 features layer1
__device__ __align__(16) float      g_als1[NN * 4];
__device__ __align__(16) float      g_ald1[NN * 4];
__device__ __align__(16) float      g_h1[(size_t)NN * HC];   // post-softmax/ELU h1 (fp32)
__device__ __align__(16) float      g_h2f[(size_t)NN * CC];
__device__            float         g_als2[NN];
__device__            float         g_ald2[NN];

// ---------------- helpers ---------------------------------------------------
__device__ __forceinline__ float lrelu(float x) { return x > 0.f ? x : 0.2f * x; }
__device__ __forceinline__ float elu1(float x)  { return x > 0.f ? x : expm1f(x); }

// ---------------- P0: edge-attr logits + degree count + edge_index output ---
// (v1e/v2e recomputed per block in shared — trivial vs. one extra launch)
__global__ void __launch_bounds__(256) k_pre(
        const float* __restrict__ eattr,
        const int* __restrict__ src, const int* __restrict__ dst,
        const float* __restrict__ W1e, const float* __restrict__ a1e,
        const float* __restrict__ W2e, const float* __restrict__ a2e,
        float* __restrict__ out_ei) {
    __shared__ float sv1[64];   // [d*4+h]
    __shared__ float sv2[16];
    int t = threadIdx.x;
    if (t < 64) {
        int d = t >> 2, h = t & 3;
        float s = 0.f;
        for (int c = 0; c < 32; c++) s += W1e[d * 128 + h * 32 + c] * a1e[h * 32 + c];
        sv1[t] = s;
    } else if (t < 80) {
        int d = t - 64;
        float s = 0.f;
        for (int c = 0; c < 32; c++) s += W2e[d * 32 + c] * a2e[c];
        sv2[d] = s;
    }
    __syncthreads();

    int e = blockIdx.x * 256 + t;
    if (e >= EPt) return;
    if (e >= EE) {
        float n = (float)(e - EE);
        out_ei[e] = n;
        out_ei[(size_t)EPt + e] = n;
        return;
    }
    float w[16];
    const float4* ep = (const float4*)(eattr + (size_t)e * EDIM);
    *(float4*)&w[0]  = ep[0];
    *(float4*)&w[4]  = ep[1];
    *(float4*)&w[8]  = ep[2];
    *(float4*)&w[12] = ep[3];
    float a0 = 0, a1 = 0, a2 = 0, a3 = 0, b = 0;
#pragma unroll
    for (int j = 0; j < 16; j++) {
        float wv = w[j];
        a0 += wv * sv1[j * 4 + 0];
        a1 += wv * sv1[j * 4 + 1];
        a2 += wv * sv1[j * 4 + 2];
        a3 += wv * sv1[j * 4 + 3];
        b  += wv * sv2[j];
    }
    *(float4*)&g_ae1[(size_t)e * 4] = make_float4(a0, a1, a2, a3);
    g_ae2[e] = b;
    int s = src[e], d = dst[e];
    atomicAdd(&g_cnt[d], 1);
    out_ei[e] = (float)s;
    out_ei[(size_t)EPt + e] = (float)d;
}

// ---------------- exclusive scan over counts (single block) ------------------
__global__ void k_scan() {
    __shared__ int sh[1024];
    const int CH = (NN + 1023) / 1024;
    int t = threadIdx.x;
    int beg = t * CH, end = min(beg + CH, NN);
    int s = 0;
    for (int i = beg; i < end; i++) s += g_cnt[i];
    sh[t] = s;
    __syncthreads();
    for (int off = 1; off < 1024; off <<= 1) {
        int v = 0;
        if (t >= off) v = sh[t - off];
        __syncthreads();
        sh[t] += v;
        __syncthreads();
    }
    int run = (t == 0) ? 0 : sh[t - 1];
    for (int i = beg; i < end; i++) { g_rs[i] = run; run += g_cnt[i]; }
    if (t == 1023) g_rs[NN] = sh[1023];
}

// ---------------- CSR fill ---------------------------------------------------
__global__ void k_fill(const int* __restrict__ src, const int* __restrict__ dst) {
    int e = blockIdx.x * 256 + threadIdx.x;
    if (e >= EE) return;
    int d = dst[e];
    int pos = g_rs[d] + atomicAdd(&g_cnt[NN + d], 1);
    g_csrc[pos] = src[e];
    g_ceid[pos] = e;
}

// ---------------- GEMM1: h1b = x @ W1 (bf16 out) + fused als1/ald1 ----------
__global__ void __launch_bounds__(256) k_gemm1(const float* __restrict__ X,
                                               const float* __restrict__ W,
                                               const float* __restrict__ a1s,
                                               const float* __restrict__ a1d) {
    __shared__ float As[8][128];
    __shared__ float Bs[8][128];
    int tid = threadIdx.x;
    int row0 = blockIdx.x * 128;
    int tm = tid >> 4, tn = tid & 15;
    float acc[8][8];
#pragma unroll
    for (int i = 0; i < 8; i++)
#pragma unroll
        for (int j = 0; j < 8; j++) acc[i][j] = 0.f;

    int lr = tid >> 1;
    int lk = (tid & 1) * 4;
    int wr = tid >> 5;
    int wc = (tid & 31) * 4;

    for (int k0 = 0; k0 < 128; k0 += 8) {
        int gr = row0 + lr;
        float4 av = (gr < NN) ? *(const float4*)&X[(size_t)gr * 128 + k0 + lk]
                              : make_float4(0, 0, 0, 0);
        As[lk + 0][lr] = av.x;
        As[lk + 1][lr] = av.y;
        As[lk + 2][lr] = av.z;
        As[lk + 3][lr] = av.w;
        *(float4*)&Bs[wr][wc] = *(const float4*)&W[(size_t)(k0 + wr) * 128 + wc];
        __syncthreads();
#pragma unroll
        for (int kk = 0; kk < 8; kk++) {
            float a[8], b[8];
            *(float4*)&a[0] = *(float4*)&As[kk][tm * 8];
            *(float4*)&a[4] = *(float4*)&As[kk][tm * 8 + 4];
            *(float4*)&b[0] = *(float4*)&Bs[kk][tn * 8];
            *(float4*)&b[4] = *(float4*)&Bs[kk][tn * 8 + 4];
#pragma unroll
            for (int i = 0; i < 8; i++)
#pragma unroll
                for (int j = 0; j < 8; j++) acc[i][j] += a[i] * b[j];
        }
        __syncthreads();
    }
    // bf16 feature store
#pragma unroll
    for (int i = 0; i < 8; i++) {
        int row = row0 + tm * 8 + i;
        if (row < NN) {
            __nv_bfloat162 p0 = __floats2bfloat162_rn(acc[i][0], acc[i][1]);
            __nv_bfloat162 p1 = __floats2bfloat162_rn(acc[i][2], acc[i][3]);
            __nv_bfloat162 p2 = __floats2bfloat162_rn(acc[i][4], acc[i][5]);
            __nv_bfloat162 p3 = __floats2bfloat162_rn(acc[i][6], acc[i][7]);
            uint4 pk;
            pk.x = *(unsigned*)&p0; pk.y = *(unsigned*)&p1;
            pk.z = *(unsigned*)&p2; pk.w = *(unsigned*)&p3;
            *(uint4*)&g_h1b[(size_t)row * 128 + tn * 8] = pk;
        }
    }
    // fused attention dots: this thread's cols tn*8..tn*8+8 all lie in head tn>>2
    float vs[8], vd[8];
#pragma unroll
    for (int j = 0; j < 8; j++) { vs[j] = a1s[tn * 8 + j]; vd[j] = a1d[tn * 8 + j]; }
    int h = tn >> 2;
#pragma unroll
    for (int i = 0; i < 8; i++) {
        float ss = 0.f, sd = 0.f;
#pragma unroll
        for (int j = 0; j < 8; j++) { ss += acc[i][j] * vs[j]; sd += acc[i][j] * vd[j]; }
        ss += __shfl_xor_sync(FULL, ss, 1);
        sd += __shfl_xor_sync(FULL, sd, 1);
        ss += __shfl_xor_sync(FULL, ss, 2);
        sd += __shfl_xor_sync(FULL, sd, 2);
        int row = row0 + tm * 8 + i;
        if ((tn & 3) == 0 && row < NN) {
            g_als1[row * 4 + h] = ss;
            g_ald1[row * 4 + h] = sd;
        }
    }
}

// ---------------- layer-1 fused softmax gather (warp per node, bf16 feats) ---
__global__ void __launch_bounds__(256) k_gather1(const float* __restrict__ b1) {
    int n = (blockIdx.x * 256 + threadIdx.x) >> 5;
    int lane = threadIdx.x & 31;
    if (n >= NN) return;
    int beg = g_rs[n], end = g_rs[n + 1];
    int deg = end - beg;
    int head = lane >> 3;      // head for feature accumulation
    int lh = lane & 3;         // head for exp computation
    int le = lane >> 2;        // edge slot 0..7
    float ald_lh = g_ald1[n * 4 + lh];
    float4 acc = make_float4(0, 0, 0, 0);
    float z = 0.f, sumae_l = 0.f;

    for (int base = beg; base < end; base += 8) {
        int m = end - base; if (m > 8) m = 8;
        int sl = 0;
        float p = 0.f;
        if (le < m) {
            sl = g_csrc[base + le];
            int el = g_ceid[base + le];
            float ae = __ldg(&g_ae1[(size_t)el * 4 + lh]);
            float als = __ldg(&g_als1[sl * 4 + lh]);
            p = __expf(lrelu(als + ald_lh + ae));
            sumae_l += ae;
        }
        for (int j = 0; j < m; j++) {
            int s = __shfl_sync(FULL, sl, j * 4);
            float pj = __shfl_sync(FULL, p, j * 4 + head);
            z += pj;
            uint2 v = *(const uint2*)&g_h1b[(size_t)s * 128 + lane * 4];
            float2 fa = __bfloat1622float2(*(__nv_bfloat162*)&v.x);
            float2 fb = __bfloat1622float2(*(__nv_bfloat162*)&v.y);
            acc.x += pj * fa.x; acc.y += pj * fa.y;
            acc.z += pj * fb.x; acc.w += pj * fb.y;
        }
    }
    // reduce sumae over edge-slot lanes (same lh)
    sumae_l += __shfl_xor_sync(FULL, sumae_l, 4);
    sumae_l += __shfl_xor_sync(FULL, sumae_l, 8);
    sumae_l += __shfl_xor_sync(FULL, sumae_l, 16);
    float sumae = __shfl_sync(FULL, sumae_l, head);

    float alsn  = g_als1[n * 4 + head];
    float ald_h = g_ald1[n * 4 + head];
    float slae = sumae / fmaxf((float)deg, 1.f);
    float ps = __expf(lrelu(alsn + ald_h + slae));
    z += ps;
    {
        uint2 v = *(const uint2*)&g_h1b[(size_t)n * 128 + lane * 4];
        float2 fa = __bfloat1622float2(*(__nv_bfloat162*)&v.x);
        float2 fb = __bfloat1622float2(*(__nv_bfloat162*)&v.y);
        acc.x += ps * fa.x; acc.y += ps * fa.y;
        acc.z += ps * fb.x; acc.w += ps * fb.y;
    }
    float inv = 1.f / z;
    float4 bv = *(const float4*)&b1[lane * 4];
    float4 o;
    o.x = elu1(acc.x * inv + bv.x);
    o.y = elu1(acc.y * inv + bv.y);
    o.z = elu1(acc.z * inv + bv.z);
    o.w = elu1(acc.w * inv + bv.w);
    *(float4*)&g_h1[(size_t)n * 128 + lane * 4] = o;
}

// ---------------- GEMM2 + fused attention dots (layer 2) --------------------
__global__ void k_gemm2(const float* __restrict__ W2,
                        const float* __restrict__ a2s, const float* __restrict__ a2d) {
    __shared__ float Ws[128 * 32];
    int tid = threadIdx.x;
    for (int i = tid; i < 128 * 32; i += 256) Ws[i] = W2[i];
    __syncthreads();
    int n = blockIdx.x * 32 + (tid >> 3);
    int c4 = (tid & 7) * 4;
    const float* hrow = &g_h1[(size_t)n * 128];
    float4 acc = make_float4(0, 0, 0, 0);
#pragma unroll 8
    for (int k = 0; k < 128; k++) {
        float hv = __ldg(&hrow[k]);
        float4 w = *(float4*)&Ws[k * 32 + c4];
        acc.x += hv * w.x;
        acc.y += hv * w.y;
        acc.z += hv * w.z;
        acc.w += hv * w.w;
    }
    *(float4*)&g_h2f[(size_t)n * 32 + c4] = acc;
    float4 vs = *(const float4*)&a2s[c4];
    float4 vd = *(const float4*)&a2d[c4];
    float ss = acc.x * vs.x + acc.y * vs.y + acc.z * vs.z + acc.w * vs.w;
    float sd = acc.x * vd.x + acc.y * vd.y + acc.z * vd.z + acc.w * vd.w;
#pragma unroll
    for (int off = 1; off < 8; off <<= 1) {
        ss += __shfl_xor_sync(FULL, ss, off);
        sd += __shfl_xor_sync(FULL, sd, off);
    }
    if ((tid & 7) == 0) { g_als2[n] = ss; g_ald2[n] = sd; }
}

// ---------------- layer-2 fused softmax gather + alpha output ----------------
__global__ void __launch_bounds__(256) k_gather2(const float* __restrict__ b2,
                                                 float* __restrict__ out_h2,
                                                 float* __restrict__ out_alpha) {
    int n = (blockIdx.x * 256 + threadIdx.x) >> 5;
    int lane = threadIdx.x & 31;
    if (n >= NN) return;
    int beg = g_rs[n], end = g_rs[n + 1];
    int deg = end - beg;
    float ald  = g_ald2[n];
    float alsn = g_als2[n];
    float acc = 0.f, z = 0.f, sumae = 0.f;

    if (deg <= 32) {
        // single chunk: keep p in registers for the alpha write
        int m = deg;
        int sl = 0, el = 0;
        float p = 0.f;
        if (lane < m) {
            sl = g_csrc[beg + lane];
            el = g_ceid[beg + lane];
            float ae = __ldg(&g_ae2[el]);
            float als = __ldg(&g_als2[sl]);
            p = __expf(lrelu(als + ald + ae));
            sumae = ae;
        }
        for (int j = 0; j < m; j++) {
            int s = __shfl_sync(FULL, sl, j);
            float pj = __shfl_sync(FULL, p, j);
            z += pj;
            acc += pj * __ldg(&g_h2f[(size_t)s * 32 + lane]);
        }
#pragma unroll
        for (int off = 16; off; off >>= 1) sumae += __shfl_xor_sync(FULL, sumae, off);
        float slae = sumae / fmaxf((float)deg, 1.f);
        float ps = __expf(lrelu(alsn + ald + slae));
        z += ps;
        acc += ps * g_h2f[(size_t)n * 32 + lane];
        float invz = 1.f / z;
        if (lane < m) out_alpha[el] = p * invz;
        if (lane == 0) out_alpha[EE + n] = ps * invz;
        out_h2[(size_t)n * 32 + lane] = elu1(acc * invz + b2[lane]);
    } else {
        for (int base = beg; base < end; base += 32) {
            int m = end - base; if (m > 32) m = 32;
            int sl = 0;
            float p = 0.f;
            if (lane < m) {
                sl = g_csrc[base + lane];
                int el = g_ceid[base + lane];
                float ae = __ldg(&g_ae2[el]);
                float als = __ldg(&g_als2[sl]);
                p = __expf(lrelu(als + ald + ae));
                sumae += ae;
            }
            for (int j = 0; j < m; j++) {
                int s = __shfl_sync(FULL, sl, j);
                float pj = __shfl_sync(FULL, p, j);
                z += pj;
                acc += pj * __ldg(&g_h2f[(size_t)s * 32 + lane]);
            }
        }
#pragma unroll
        for (int off = 16; off; off >>= 1) sumae += __shfl_xor_sync(FULL, sumae, off);
        float slae = sumae / fmaxf((float)deg, 1.f);
        float ps = __expf(lrelu(alsn + ald + slae));
        z += ps;
        acc += ps * g_h2f[(size_t)n * 32 + lane];
        float invz = 1.f / z;
        // second pass: recompute p, write alpha
        for (int base = beg; base < end; base += 32) {
            int m = end - base; if (m > 32) m = 32;
            if (lane < m) {
                int sl = g_csrc[base + lane];
                int el = g_ceid[base + lane];
                float p = __expf(lrelu(__ldg(&g_als2[sl]) + ald + __ldg(&g_ae2[el])));
                out_alpha[el] = p * invz;
            }
        }
        if (lane == 0) out_alpha[EE + n] = ps * invz;
        out_h2[(size_t)n * 32 + lane] = elu1(acc * invz + b2[lane]);
    }
}

// ---------------- launcher ---------------------------------------------------
static inline int dgrid(long n, int b) { return (int)((n + b - 1) / b); }

extern "C" void kernel_launch(void* const* d_in, const int* in_sizes, int n_in,
                              void* d_out, int out_size) {
    const float* x     = (const float*)d_in[0];
    const int*   ei    = (const int*)d_in[1];
    const int*   src   = ei;
    const int*   dst   = ei + EE;
    const float* eattr = (const float*)d_in[2];
    const float* W1    = (const float*)d_in[3];
    const float* W1e   = (const float*)d_in[4];
    const float* a1s   = (const float*)d_in[5];
    const float* a1d   = (const float*)d_in[6];
    const float* a1e   = (const float*)d_in[7];
    const float* b1    = (const float*)d_in[8];
    const float* W2    = (const float*)d_in[9];
    const float* W2e   = (const float*)d_in[10];
    const float* a2s   = (const float*)d_in[11];
    const float* a2d   = (const float*)d_in[12];
    const float* a2e   = (const float*)d_in[13];
    const float* b2    = (const float*)d_in[14];

    float* out       = (float*)d_out;
    float* out_h2    = out;                                  // N*32
    float* out_ei    = out + (size_t)NN * CC;                // 2*EPt
    float* out_alpha = out_ei + 2 * (size_t)EPt;             // EPt

    void* p;
    cudaGetSymbolAddress(&p, g_cnt);
    cudaMemsetAsync(p, 0, (size_t)2 * NN * 4);

    k_pre<<<dgrid(EPt, 256), 256>>>(eattr, src, dst, W1e, a1e, W2e, a2e, out_ei);
    k_scan<<<1, 1024>>>();
    k_fill<<<dgrid(EE, 256), 256>>>(src, dst);
    k_gemm1<<<dgrid(NN, 128), 256>>>(x, W1, a1s, a1d);
    k_gather1<<<dgrid((long)NN * 32, 256), 256>>>(b1);       // 6th launch -> profiled
    k_gemm2<<<NN / 32, 256>>>(W2, a2s, a2d);
    k_gather2<<<dgrid((long)NN * 32, 256), 256>>>(b2, out_h2, out_alpha);
}

// round 8
// speedup vs baseline: 1.9468x; 1.0189x over previous
#include <cuda_runtime.h>
#include <cuda_fp16.h>

#define NN 100000
#define EE 1600000
#define EPt 1700000     // EE + NN (with self loops)
#define HC 128          // H*C layer1
#define CC 32
#define EDIM 16
#define FULL 0xffffffffu

typedef unsigned long long u64;

// ---------------- scratch (static device allocations) -----------------------
__device__            int      g_cnt[2 * NN];        // [0,NN)=count, [NN,2NN)=cursor
__device__            int      g_rs[NN + 1];         // CSR row starts (by dst)
__device__ __align__(16) int2  g_cse[EE];            // CSR (src, edge-id) pairs
__device__ __align__(16) float g_ae1[(size_t)EE * 4];
__device__            float    g_ae2[EE];
__device__ __align__(16) __half g_h1h[(size_t)NN * HC];  // fp16 features layer1
__device__ __align__(16) float g_als1[NN * 4];
__device__ __align__(16) float g_ald1[NN * 4];
__device__ __align__(16) float g_h1[(size_t)NN * HC];   // post-softmax/ELU h1 (fp32)
__device__ __align__(16) float g_h2f[(size_t)NN * CC];
__device__            float    g_als2[NN];
__device__            float    g_ald2[NN];

// ---------------- helpers ---------------------------------------------------
__device__ __forceinline__ float lrelu(float x) { return x > 0.f ? x : 0.2f * x; }
__device__ __forceinline__ float elu1(float x)  { return x > 0.f ? x : expm1f(x); }
__device__ __forceinline__ u64 pack2(float x, float y) {
    u64 r; asm("mov.b64 %0, {%1, %2};" : "=l"(r) : "f"(x), "f"(y)); return r;
}
__device__ __forceinline__ float2 unpack2(u64 v) {
    float2 f; asm("mov.b64 {%0, %1}, %2;" : "=f"(f.x), "=f"(f.y) : "l"(v)); return f;
}
__device__ __forceinline__ void fma2(u64& d, u64 a, u64 b) {
    asm("fma.rn.f32x2 %0, %1, %2, %0;" : "+l"(d) : "l"(a), "l"(b));
}

// ---------------- P0: edge-attr logits + degree count + edge_index output ---
__global__ void __launch_bounds__(256) k_pre(
        const float* __restrict__ eattr,
        const int* __restrict__ src, const int* __restrict__ dst,
        const float* __restrict__ W1e, const float* __restrict__ a1e,
        const float* __restrict__ W2e, const float* __restrict__ a2e,
        float* __restrict__ out_ei) {
    __shared__ float sv1[64];   // [d*4+h]
    __shared__ float sv2[16];
    int t = threadIdx.x;
    if (t < 64) {
        int d = t >> 2, h = t & 3;
        float s = 0.f;
        for (int c = 0; c < 32; c++) s += W1e[d * 128 + h * 32 + c] * a1e[h * 32 + c];
        sv1[t] = s;
    } else if (t < 80) {
        int d = t - 64;
        float s = 0.f;
        for (int c = 0; c < 32; c++) s += W2e[d * 32 + c] * a2e[c];
        sv2[d] = s;
    }
    __syncthreads();

    int e = blockIdx.x * 256 + t;
    if (e >= EPt) return;
    if (e >= EE) {
        float n = (float)(e - EE);
        out_ei[e] = n;
        out_ei[(size_t)EPt + e] = n;
        return;
    }
    float w[16];
    const float4* ep = (const float4*)(eattr + (size_t)e * EDIM);
    *(float4*)&w[0]  = ep[0];
    *(float4*)&w[4]  = ep[1];
    *(float4*)&w[8]  = ep[2];
    *(float4*)&w[12] = ep[3];
    float a0 = 0, a1 = 0, a2 = 0, a3 = 0, b = 0;
#pragma unroll
    for (int j = 0; j < 16; j++) {
        float wv = w[j];
        a0 += wv * sv1[j * 4 + 0];
        a1 += wv * sv1[j * 4 + 1];
        a2 += wv * sv1[j * 4 + 2];
        a3 += wv * sv1[j * 4 + 3];
        b  += wv * sv2[j];
    }
    *(float4*)&g_ae1[(size_t)e * 4] = make_float4(a0, a1, a2, a3);
    g_ae2[e] = b;
    int s = src[e], d = dst[e];
    atomicAdd(&g_cnt[d], 1);
    out_ei[e] = (float)s;
    out_ei[(size_t)EPt + e] = (float)d;
}

// ---------------- exclusive scan over counts (single block) ------------------
__global__ void k_scan() {
    __shared__ int sh[1024];
    const int CH = (NN + 1023) / 1024;
    int t = threadIdx.x;
    int beg = t * CH, end = min(beg + CH, NN);
    int s = 0;
    for (int i = beg; i < end; i++) s += g_cnt[i];
    sh[t] = s;
    __syncthreads();
    for (int off = 1; off < 1024; off <<= 1) {
        int v = 0;
        if (t >= off) v = sh[t - off];
        __syncthreads();
        sh[t] += v;
        __syncthreads();
    }
    int run = (t == 0) ? 0 : sh[t - 1];
    for (int i = beg; i < end; i++) { g_rs[i] = run; run += g_cnt[i]; }
    if (t == 1023) g_rs[NN] = sh[1023];
}

// ---------------- CSR fill (paired int2 scatter) ------------------------------
__global__ void k_fill(const int* __restrict__ src, const int* __restrict__ dst) {
    int e = blockIdx.x * 256 + threadIdx.x;
    if (e >= EE) return;
    int d = dst[e];
    int pos = g_rs[d] + atomicAdd(&g_cnt[NN + d], 1);
    g_cse[pos] = make_int2(src[e], e);
}

// ---------------- GEMM1: h1h = x @ W1 (fp16 out) + fused als1/ald1 ----------
// FFMA2 (fma.rn.f32x2) inner loop: 32 packed FMA per k-step per thread.
__global__ void __launch_bounds__(256) k_gemm1(const float* __restrict__ X,
                                               const float* __restrict__ W,
                                               const float* __restrict__ a1s,
                                               const float* __restrict__ a1d) {
    __shared__ float As[8][128];
    __shared__ float Bs[8][128];
    int tid = threadIdx.x;
    int row0 = blockIdx.x * 128;
    int tm = tid >> 4, tn = tid & 15;
    u64 acc2[8][4];
#pragma unroll
    for (int i = 0; i < 8; i++)
#pragma unroll
        for (int j = 0; j < 4; j++) acc2[i][j] = 0ull;

    int lr = tid >> 1;
    int lk = (tid & 1) * 4;
    int wr = tid >> 5;
    int wc = (tid & 31) * 4;

    for (int k0 = 0; k0 < 128; k0 += 8) {
        int gr = row0 + lr;
        float4 av = (gr < NN) ? *(const float4*)&X[(size_t)gr * 128 + k0 + lk]
                              : make_float4(0, 0, 0, 0);
        As[lk + 0][lr] = av.x;
        As[lk + 1][lr] = av.y;
        As[lk + 2][lr] = av.z;
        As[lk + 3][lr] = av.w;
        *(float4*)&Bs[wr][wc] = *(const float4*)&W[(size_t)(k0 + wr) * 128 + wc];
        __syncthreads();
#pragma unroll
        for (int kk = 0; kk < 8; kk++) {
            float a[8];
            *(float4*)&a[0] = *(float4*)&As[kk][tm * 8];
            *(float4*)&a[4] = *(float4*)&As[kk][tm * 8 + 4];
            ulonglong2 b01 = *(ulonglong2*)&Bs[kk][tn * 8];
            ulonglong2 b23 = *(ulonglong2*)&Bs[kk][tn * 8 + 4];
#pragma unroll
            for (int i = 0; i < 8; i++) {
                u64 ai = pack2(a[i], a[i]);
                fma2(acc2[i][0], ai, b01.x);
                fma2(acc2[i][1], ai, b01.y);
                fma2(acc2[i][2], ai, b23.x);
                fma2(acc2[i][3], ai, b23.y);
            }
        }
        __syncthreads();
    }
    // unpack accumulators
    float acc[8][8];
#pragma unroll
    for (int i = 0; i < 8; i++)
#pragma unroll
        for (int j = 0; j < 4; j++) {
            float2 f = unpack2(acc2[i][j]);
            acc[i][2 * j] = f.x; acc[i][2 * j + 1] = f.y;
        }
    // fp16 feature store
#pragma unroll
    for (int i = 0; i < 8; i++) {
        int row = row0 + tm * 8 + i;
        if (row < NN) {
            __half2 p0 = __floats2half2_rn(acc[i][0], acc[i][1]);
            __half2 p1 = __floats2half2_rn(acc[i][2], acc[i][3]);
            __half2 p2 = __floats2half2_rn(acc[i][4], acc[i][5]);
            __half2 p3 = __floats2half2_rn(acc[i][6], acc[i][7]);
            uint4 pk;
            pk.x = *(unsigned*)&p0; pk.y = *(unsigned*)&p1;
            pk.z = *(unsigned*)&p2; pk.w = *(unsigned*)&p3;
            *(uint4*)&g_h1h[(size_t)row * 128 + tn * 8] = pk;
        }
    }
    // fused attention dots: this thread's cols tn*8..tn*8+8 lie in head tn>>2
    float vs[8], vd[8];
#pragma unroll
    for (int j = 0; j < 8; j++) { vs[j] = a1s[tn * 8 + j]; vd[j] = a1d[tn * 8 + j]; }
    int h = tn >> 2;
#pragma unroll
    for (int i = 0; i < 8; i++) {
        float ss = 0.f, sd = 0.f;
#pragma unroll
        for (int j = 0; j < 8; j++) { ss += acc[i][j] * vs[j]; sd += acc[i][j] * vd[j]; }
        ss += __shfl_xor_sync(FULL, ss, 1);
        sd += __shfl_xor_sync(FULL, sd, 1);
        ss += __shfl_xor_sync(FULL, ss, 2);
        sd += __shfl_xor_sync(FULL, sd, 2);
        int row = row0 + tm * 8 + i;
        if ((tn & 3) == 0 && row < NN) {
            g_als1[row * 4 + h] = ss;
            g_ald1[row * 4 + h] = sd;
        }
    }
}

// ---------------- layer-1 fused softmax gather (warp per node, fp16 feats) ---
__global__ void __launch_bounds__(256) k_gather1(const float* __restrict__ b1) {
    int n = (blockIdx.x * 256 + threadIdx.x) >> 5;
    int lane = threadIdx.x & 31;
    if (n >= NN) return;
    int beg = g_rs[n], end = g_rs[n + 1];
    int deg = end - beg;
    int head = lane >> 3;      // head for feature accumulation
    int lh = lane & 3;         // head for exp computation
    int le = lane >> 2;        // edge slot 0..7
    float ald_lh = g_ald1[n * 4 + lh];
    float4 acc = make_float4(0, 0, 0, 0);
    float z = 0.f, sumae_l = 0.f;

    for (int base = beg; base < end; base += 8) {
        int m = end - base; if (m > 8) m = 8;
        int sl = 0;
        float p = 0.f;
        if (le < m) {
            int2 se = g_cse[base + le];
            sl = se.x;
            float ae = __ldg(&g_ae1[(size_t)se.y * 4 + lh]);
            float als = __ldg(&g_als1[sl * 4 + lh]);
            p = __expf(lrelu(als + ald_lh + ae));
            sumae_l += ae;
        }
        for (int j = 0; j < m; j++) {
            int s = __shfl_sync(FULL, sl, j * 4);
            float pj = __shfl_sync(FULL, p, j * 4 + head);
            z += pj;
            uint2 v = *(const uint2*)&g_h1h[(size_t)s * 128 + lane * 4];
            float2 fa = __half22float2(*(__half2*)&v.x);
            float2 fb = __half22float2(*(__half2*)&v.y);
            acc.x += pj * fa.x; acc.y += pj * fa.y;
            acc.z += pj * fb.x; acc.w += pj * fb.y;
        }
    }
    sumae_l += __shfl_xor_sync(FULL, sumae_l, 4);
    sumae_l += __shfl_xor_sync(FULL, sumae_l, 8);
    sumae_l += __shfl_xor_sync(FULL, sumae_l, 16);
    float sumae = __shfl_sync(FULL, sumae_l, head);

    float alsn  = g_als1[n * 4 + head];
    float ald_h = g_ald1[n * 4 + head];
    float slae = sumae / fmaxf((float)deg, 1.f);
    float ps = __expf(lrelu(alsn + ald_h + slae));
    z += ps;
    {
        uint2 v = *(const uint2*)&g_h1h[(size_t)n * 128 + lane * 4];
        float2 fa = __half22float2(*(__half2*)&v.x);
        float2 fb = __half22float2(*(__half2*)&v.y);
        acc.x += ps * fa.x; acc.y += ps * fa.y;
        acc.z += ps * fb.x; acc.w += ps * fb.y;
    }
    float inv = 1.f / z;
    float4 bv = *(const float4*)&b1[lane * 4];
    float4 o;
    o.x = elu1(acc.x * inv + bv.x);
    o.y = elu1(acc.y * inv + bv.y);
    o.z = elu1(acc.z * inv + bv.z);
    o.w = elu1(acc.w * inv + bv.w);
    *(float4*)&g_h1[(size_t)n * 128 + lane * 4] = o;
}

// ---------------- GEMM2 + fused attention dots (layer 2) --------------------
__global__ void k_gemm2(const float* __restrict__ W2,
                        const float* __restrict__ a2s, const float* __restrict__ a2d) {
    __shared__ float Ws[128 * 32];
    int tid = threadIdx.x;
    for (int i = tid; i < 128 * 32; i += 256) Ws[i] = W2[i];
    __syncthreads();
    int n = blockIdx.x * 32 + (tid >> 3);
    int c4 = (tid & 7) * 4;
    const float* hrow = &g_h1[(size_t)n * 128];
    float4 acc = make_float4(0, 0, 0, 0);
#pragma unroll 8
    for (int k = 0; k < 128; k++) {
        float hv = __ldg(&hrow[k]);
        float4 w = *(float4*)&Ws[k * 32 + c4];
        acc.x += hv * w.x;
        acc.y += hv * w.y;
        acc.z += hv * w.z;
        acc.w += hv * w.w;
    }
    *(float4*)&g_h2f[(size_t)n * 32 + c4] = acc;
    float4 vs = *(const float4*)&a2s[c4];
    float4 vd = *(const float4*)&a2d[c4];
    float ss = acc.x * vs.x + acc.y * vs.y + acc.z * vs.z + acc.w * vs.w;
    float sd = acc.x * vd.x + acc.y * vd.y + acc.z * vd.z + acc.w * vd.w;
#pragma unroll
    for (int off = 1; off < 8; off <<= 1) {
        ss += __shfl_xor_sync(FULL, ss, off);
        sd += __shfl_xor_sync(FULL, sd, off);
    }
    if ((tid & 7) == 0) { g_als2[n] = ss; g_ald2[n] = sd; }
}

// ---------------- layer-2 fused softmax gather + alpha output ----------------
__global__ void __launch_bounds__(256) k_gather2(const float* __restrict__ b2,
                                                 float* __restrict__ out_h2,
                                                 float* __restrict__ out_alpha) {
    int n = (blockIdx.x * 256 + threadIdx.x) >> 5;
    int lane = threadIdx.x & 31;
    if (n >= NN) return;
    int beg = g_rs[n], end = g_rs[n + 1];
    int deg = end - beg;
    float ald  = g_ald2[n];
    float alsn = g_als2[n];
    float acc = 0.f, z = 0.f, sumae = 0.f;

    if (deg <= 32) {
        int m = deg;
        int sl = 0, el = 0;
        float p = 0.f;
        if (lane < m) {
            int2 se = g_cse[beg + lane];
            sl = se.x; el = se.y;
            float ae = __ldg(&g_ae2[el]);
            float als = __ldg(&g_als2[sl]);
            p = __expf(lrelu(als + ald + ae));
            sumae = ae;
        }
        for (int j = 0; j < m; j++) {
            int s = __shfl_sync(FULL, sl, j);
            float pj = __shfl_sync(FULL, p, j);
            z += pj;
            acc += pj * __ldg(&g_h2f[(size_t)s * 32 + lane]);
        }
#pragma unroll
        for (int off = 16; off; off >>= 1) sumae += __shfl_xor_sync(FULL, sumae, off);
        float slae = sumae / fmaxf((float)deg, 1.f);
        float ps = __expf(lrelu(alsn + ald + slae));
        z += ps;
        acc += ps * g_h2f[(size_t)n * 32 + lane];
        float invz = 1.f / z;
        if (lane < m) out_alpha[el] = p * invz;
        if (lane == 0) out_alpha[EE + n] = ps * invz;
        out_h2[(size_t)n * 32 + lane] = elu1(acc * invz + b2[lane]);
    } else {
        for (int base = beg; base < end; base += 32) {
            int m = end - base; if (m > 32) m = 32;
            int sl = 0;
            float p = 0.f;
            if (lane < m) {
                int2 se = g_cse[base + lane];
                sl = se.x;
                float ae = __ldg(&g_ae2[se.y]);
                float als = __ldg(&g_als2[sl]);
                p = __expf(lrelu(als + ald + ae));
                sumae += ae;
            }
            for (int j = 0; j < m; j++) {
                int s = __shfl_sync(FULL, sl, j);
                float pj = __shfl_sync(FULL, p, j);
                z += pj;
                acc += pj * __ldg(&g_h2f[(size_t)s * 32 + lane]);
            }
        }
#pragma unroll
        for (int off = 16; off; off >>= 1) sumae += __shfl_xor_sync(FULL, sumae, off);
        float slae = sumae / fmaxf((float)deg, 1.f);
        float ps = __expf(lrelu(alsn + ald + slae));
        z += ps;
        acc += ps * g_h2f[(size_t)n * 32 + lane];
        float invz = 1.f / z;
        for (int base = beg; base < end; base += 32) {
            int m = end - base; if (m > 32) m = 32;
            if (lane < m) {
                int2 se = g_cse[base + lane];
                float p = __expf(lrelu(__ldg(&g_als2[se.x]) + ald + __ldg(&g_ae2[se.y])));
                out_alpha[se.y] = p * invz;
            }
        }
        if (lane == 0) out_alpha[EE + n] = ps * invz;
        out_h2[(size_t)n * 32 + lane] = elu1(acc * invz + b2[lane]);
    }
}

// ---------------- launcher ---------------------------------------------------
static inline int dgrid(long n, int b) { return (int)((n + b - 1) / b); }

extern "C" void kernel_launch(void* const* d_in, const int* in_sizes, int n_in,
                              void* d_out, int out_size) {
    const float* x     = (const float*)d_in[0];
    const int*   ei    = (const int*)d_in[1];
    const int*   src   = ei;
    const int*   dst   = ei + EE;
    const float* eattr = (const float*)d_in[2];
    const float* W1    = (const float*)d_in[3];
    const float* W1e   = (const float*)d_in[4];
    const float* a1s   = (const float*)d_in[5];
    const float* a1d   = (const float*)d_in[6];
    const float* a1e   = (const float*)d_in[7];
    const float* b1    = (const float*)d_in[8];
    const float* W2    = (const float*)d_in[9];
    const float* W2e   = (const float*)d_in[10];
    const float* a2s   = (const float*)d_in[11];
    const float* a2d   = (const float*)d_in[12];
    const float* a2e   = (const float*)d_in[13];
    const float* b2    = (const float*)d_in[14];

    float* out       = (float*)d_out;
    float* out_h2    = out;                                  // N*32
    float* out_ei    = out + (size_t)NN * CC;                // 2*EPt
    float* out_alpha = out_ei + 2 * (size_t)EPt;             // EPt

    void* p;
    cudaGetSymbolAddress(&p, g_cnt);
    cudaMemsetAsync(p, 0, (size_t)2 * NN * 4);

    k_pre<<<dgrid(EPt, 256), 256>>>(eattr, src, dst, W1e, a1e, W2e, a2e, out_ei);
    k_scan<<<1, 1024>>>();
    k_fill<<<dgrid(EE, 256), 256>>>(src, dst);
    k_gemm1<<<dgrid(NN, 128), 256>>>(x, W1, a1s, a1d);
    k_gather1<<<dgrid((long)NN * 32, 256), 256>>>(b1);       // 6th launch -> profiled
    k_gemm2<<<NN / 32, 256>>>(W2, a2s, a2d);
    k_gather2<<<dgrid((long)NN * 32, 256), 256>>>(b2, out_h2, out_alpha);
}

// round 9
// speedup vs baseline: 2.1154x; 1.0866x over previous
#include <cuda_runtime.h>
#include <cuda_fp16.h>

#define NN 100000
#define EE 1600000
#define EPt 1700000     // EE + NN (with self loops)
#define HC 128          // H*C layer1
#define CC 32
#define EDIM 16
#define FULL 0xffffffffu

// ---------------- scratch (static device allocations) -----------------------
__device__            int      g_cnt[2 * NN];        // [0,NN)=count, [NN,2NN)=cursor
__device__            int      g_rs[NN + 1];         // CSR row starts (by dst)
__device__ __align__(16) int2  g_cse[EE];            // CSR (src, edge-id) pairs
__device__ __align__(16) float g_ae1[(size_t)EE * 4];
__device__            float    g_ae2[EE];
__device__ __align__(16) __half g_h1h[(size_t)NN * HC];  // fp16 features layer1
__device__ __align__(16) float g_als1[NN * 4];
__device__ __align__(16) float g_ald1[NN * 4];
__device__ __align__(16) float g_h1[(size_t)NN * HC];   // post-softmax/ELU h1 (fp32)
__device__ __align__(16) float g_h2f[(size_t)NN * CC];
__device__            float    g_als2[NN];
__device__            float    g_ald2[NN];

// ---------------- helpers ---------------------------------------------------
__device__ __forceinline__ float lrelu(float x) { return x > 0.f ? x : 0.2f * x; }
__device__ __forceinline__ float elu1(float x)  { return x > 0.f ? x : expm1f(x); }
__device__ __forceinline__ unsigned tf32cvt(float f) {
    unsigned u; asm("cvt.rna.tf32.f32 %0, %1;" : "=r"(u) : "f"(f)); return u;
}
__device__ __forceinline__ void mma_tf32(float* c, const unsigned* a, const unsigned* b) {
    asm("mma.sync.aligned.m16n8k8.row.col.f32.tf32.tf32.f32 "
        "{%0,%1,%2,%3}, {%4,%5,%6,%7}, {%8,%9}, {%0,%1,%2,%3};"
        : "+f"(c[0]), "+f"(c[1]), "+f"(c[2]), "+f"(c[3])
        : "r"(a[0]), "r"(a[1]), "r"(a[2]), "r"(a[3]), "r"(b[0]), "r"(b[1]));
}

// ---------------- P0: edge-attr logits + degree count + edge_index output ---
__global__ void __launch_bounds__(256) k_pre(
        const float* __restrict__ eattr,
        const int* __restrict__ src, const int* __restrict__ dst,
        const float* __restrict__ W1e, const float* __restrict__ a1e,
        const float* __restrict__ W2e, const float* __restrict__ a2e,
        float* __restrict__ out_ei) {
    __shared__ float sv1[64];   // [d*4+h]
    __shared__ float sv2[16];
    int t = threadIdx.x;
    if (t < 64) {
        int d = t >> 2, h = t & 3;
        float s = 0.f;
        for (int c = 0; c < 32; c++) s += W1e[d * 128 + h * 32 + c] * a1e[h * 32 + c];
        sv1[t] = s;
    } else if (t < 80) {
        int d = t - 64;
        float s = 0.f;
        for (int c = 0; c < 32; c++) s += W2e[d * 32 + c] * a2e[c];
        sv2[d] = s;
    }
    __syncthreads();

    int e = blockIdx.x * 256 + t;
    if (e >= EPt) return;
    if (e >= EE) {
        float n = (float)(e - EE);
        out_ei[e] = n;
        out_ei[(size_t)EPt + e] = n;
        return;
    }
    float w[16];
    const float4* ep = (const float4*)(eattr + (size_t)e * EDIM);
    *(float4*)&w[0]  = ep[0];
    *(float4*)&w[4]  = ep[1];
    *(float4*)&w[8]  = ep[2];
    *(float4*)&w[12] = ep[3];
    float a0 = 0, a1 = 0, a2 = 0, a3 = 0, b = 0;
#pragma unroll
    for (int j = 0; j < 16; j++) {
        float wv = w[j];
        a0 += wv * sv1[j * 4 + 0];
        a1 += wv * sv1[j * 4 + 1];
        a2 += wv * sv1[j * 4 + 2];
        a3 += wv * sv1[j * 4 + 3];
        b  += wv * sv2[j];
    }
    *(float4*)&g_ae1[(size_t)e * 4] = make_float4(a0, a1, a2, a3);
    g_ae2[e] = b;
    int s = src[e], d = dst[e];
    atomicAdd(&g_cnt[d], 1);
    out_ei[e] = (float)s;
    out_ei[(size_t)EPt + e] = (float)d;
}

// ---------------- exclusive scan over counts (single block) ------------------
__global__ void k_scan() {
    __shared__ int sh[1024];
    const int CH = (NN + 1023) / 1024;
    int t = threadIdx.x;
    int beg = t * CH, end = min(beg + CH, NN);
    int s = 0;
    for (int i = beg; i < end; i++) s += g_cnt[i];
    sh[t] = s;
    __syncthreads();
    for (int off = 1; off < 1024; off <<= 1) {
        int v = 0;
        if (t >= off) v = sh[t - off];
        __syncthreads();
        sh[t] += v;
        __syncthreads();
    }
    int run = (t == 0) ? 0 : sh[t - 1];
    for (int i = beg; i < end; i++) { g_rs[i] = run; run += g_cnt[i]; }
    if (t == 1023) g_rs[NN] = sh[1023];
}

// ---------------- CSR fill (paired int2 scatter) ------------------------------
__global__ void k_fill(const int* __restrict__ src, const int* __restrict__ dst) {
    int e = blockIdx.x * 256 + threadIdx.x;
    if (e >= EE) return;
    int d = dst[e];
    int pos = g_rs[d] + atomicAdd(&g_cnt[NN + d], 1);
    g_cse[pos] = make_int2(src[e], e);
}

// ---------------- GEMM1 (tf32 tensor-core): h1h = x @ W1 + fused als1/ald1 --
// Block tile 128x128, 8 warps in 4(M)x2(N); warp tile 32x64; m16n8k8 atoms.
__global__ void __launch_bounds__(256) k_gemm1(const float* __restrict__ X,
                                               const float* __restrict__ W,
                                               const float* __restrict__ a1s,
                                               const float* __restrict__ a1d) {
    __shared__ unsigned As[16][136];   // tf32 bits, [k][m], bank-conflict-free
    __shared__ unsigned Bs[16][136];   // tf32 bits, [k][n]
    int tid = threadIdx.x;
    int lane = tid & 31, wid = tid >> 5;
    int g = lane >> 2, c = lane & 3;
    int wm = wid >> 1, wn = wid & 1;
    int row0 = blockIdx.x * 128;

    float C[2][8][4];
#pragma unroll
    for (int am = 0; am < 2; am++)
#pragma unroll
        for (int an = 0; an < 8; an++)
#pragma unroll
            for (int q = 0; q < 4; q++) C[am][an][q] = 0.f;

    int lr = tid >> 1;          // A row within tile 0..127
    int lk = (tid & 1) * 4;     // A k offset {0,4}
    int wr = tid >> 5;          // B k row 0..7
    int wc = (tid & 31) * 4;    // B col

    for (int k0 = 0; k0 < 128; k0 += 16) {
        int gr = row0 + lr;
        float4 av0 = (gr < NN) ? *(const float4*)&X[(size_t)gr * 128 + k0 + lk]
                               : make_float4(0, 0, 0, 0);
        float4 av1 = (gr < NN) ? *(const float4*)&X[(size_t)gr * 128 + k0 + lk + 8]
                               : make_float4(0, 0, 0, 0);
        As[lk + 0][lr] = tf32cvt(av0.x);
        As[lk + 1][lr] = tf32cvt(av0.y);
        As[lk + 2][lr] = tf32cvt(av0.z);
        As[lk + 3][lr] = tf32cvt(av0.w);
        As[lk + 8][lr]  = tf32cvt(av1.x);
        As[lk + 9][lr]  = tf32cvt(av1.y);
        As[lk + 10][lr] = tf32cvt(av1.z);
        As[lk + 11][lr] = tf32cvt(av1.w);
        float4 bv0 = *(const float4*)&W[(size_t)(k0 + wr) * 128 + wc];
        float4 bv1 = *(const float4*)&W[(size_t)(k0 + wr + 8) * 128 + wc];
        uint4 bu0 = make_uint4(tf32cvt(bv0.x), tf32cvt(bv0.y), tf32cvt(bv0.z), tf32cvt(bv0.w));
        uint4 bu1 = make_uint4(tf32cvt(bv1.x), tf32cvt(bv1.y), tf32cvt(bv1.z), tf32cvt(bv1.w));
        *(uint4*)&Bs[wr][wc]     = bu0;
        *(uint4*)&Bs[wr + 8][wc] = bu1;
        __syncthreads();
#pragma unroll
        for (int kk = 0; kk < 16; kk += 8) {
            unsigned bf[8][2];
#pragma unroll
            for (int an = 0; an < 8; an++) {
                int n0 = wn * 64 + an * 8 + g;
                bf[an][0] = Bs[kk + c][n0];
                bf[an][1] = Bs[kk + c + 4][n0];
            }
            unsigned af[2][4];
#pragma unroll
            for (int am = 0; am < 2; am++) {
                int m0 = wm * 32 + am * 16 + g;
                af[am][0] = As[kk + c][m0];
                af[am][1] = As[kk + c][m0 + 8];
                af[am][2] = As[kk + c + 4][m0];
                af[am][3] = As[kk + c + 4][m0 + 8];
            }
#pragma unroll
            for (int am = 0; am < 2; am++)
#pragma unroll
                for (int an = 0; an < 8; an++)
                    mma_tf32(C[am][an], af[am], bf[an]);
        }
        __syncthreads();
    }

    // epilogue: fp16 feature store + fused attention dots
#pragma unroll
    for (int am = 0; am < 2; am++) {
#pragma unroll
        for (int rh = 0; rh < 2; rh++) {
            int row = row0 + wm * 32 + am * 16 + rh * 8 + g;
            bool ok = row < NN;
            float ss0 = 0.f, sd0 = 0.f, ss1 = 0.f, sd1 = 0.f;   // two heads in this warp's 64 cols
#pragma unroll
            for (int an = 0; an < 8; an++) {
                float c0 = C[am][an][rh * 2 + 0];
                float c1 = C[am][an][rh * 2 + 1];
                int col = wn * 64 + an * 8 + 2 * c;
                if (ok) {
                    __half2 hv = __floats2half2_rn(c0, c1);
                    *(unsigned*)&g_h1h[(size_t)row * 128 + col] = *(unsigned*)&hv;
                }
                float w0 = a1s[col], w1 = a1s[col + 1];
                float u0 = a1d[col], u1 = a1d[col + 1];
                if (an < 4) { ss0 += c0 * w0 + c1 * w1; sd0 += c0 * u0 + c1 * u1; }
                else        { ss1 += c0 * w0 + c1 * w1; sd1 += c0 * u0 + c1 * u1; }
            }
            // reduce over the 4 lanes of the group (c = 0..3)
            ss0 += __shfl_xor_sync(FULL, ss0, 1); sd0 += __shfl_xor_sync(FULL, sd0, 1);
            ss0 += __shfl_xor_sync(FULL, ss0, 2); sd0 += __shfl_xor_sync(FULL, sd0, 2);
            ss1 += __shfl_xor_sync(FULL, ss1, 1); sd1 += __shfl_xor_sync(FULL, sd1, 1);
            ss1 += __shfl_xor_sync(FULL, ss1, 2); sd1 += __shfl_xor_sync(FULL, sd1, 2);
            if (c == 0 && ok) {
                int h0 = wn * 2;
                g_als1[row * 4 + h0] = ss0;
                g_ald1[row * 4 + h0] = sd0;
                g_als1[row * 4 + h0 + 1] = ss1;
                g_ald1[row * 4 + h0 + 1] = sd1;
            }
        }
    }
}

// ---------------- layer-1 fused softmax gather (warp per node, fp16 feats) ---
__global__ void __launch_bounds__(256) k_gather1(const float* __restrict__ b1) {
    int n = (blockIdx.x * 256 + threadIdx.x) >> 5;
    int lane = threadIdx.x & 31;
    if (n >= NN) return;
    int beg = g_rs[n], end = g_rs[n + 1];
    int deg = end - beg;
    int head = lane >> 3;      // head for feature accumulation
    int lh = lane & 3;         // head for exp computation
    int le = lane >> 2;        // edge slot 0..7
    float ald_lh = g_ald1[n * 4 + lh];
    float4 acc = make_float4(0, 0, 0, 0);
    float z = 0.f, sumae_l = 0.f;

    for (int base = beg; base < end; base += 8) {
        int m = end - base; if (m > 8) m = 8;
        int sl = 0;
        float p = 0.f;
        if (le < m) {
            int2 se = g_cse[base + le];
            sl = se.x;
            float ae = __ldg(&g_ae1[(size_t)se.y * 4 + lh]);
            float als = __ldg(&g_als1[sl * 4 + lh]);
            p = __expf(lrelu(als + ald_lh + ae));
            sumae_l += ae;
        }
        for (int j = 0; j < m; j++) {
            int s = __shfl_sync(FULL, sl, j * 4);
            float pj = __shfl_sync(FULL, p, j * 4 + head);
            z += pj;
            uint2 v = *(const uint2*)&g_h1h[(size_t)s * 128 + lane * 4];
            float2 fa = __half22float2(*(__half2*)&v.x);
            float2 fb = __half22float2(*(__half2*)&v.y);
            acc.x += pj * fa.x; acc.y += pj * fa.y;
            acc.z += pj * fb.x; acc.w += pj * fb.y;
        }
    }
    sumae_l += __shfl_xor_sync(FULL, sumae_l, 4);
    sumae_l += __shfl_xor_sync(FULL, sumae_l, 8);
    sumae_l += __shfl_xor_sync(FULL, sumae_l, 16);
    float sumae = __shfl_sync(FULL, sumae_l, head);

    float alsn  = g_als1[n * 4 + head];
    float ald_h = g_ald1[n * 4 + head];
    float slae = sumae / fmaxf((float)deg, 1.f);
    float ps = __expf(lrelu(alsn + ald_h + slae));
    z += ps;
    {
        uint2 v = *(const uint2*)&g_h1h[(size_t)n * 128 + lane * 4];
        float2 fa = __half22float2(*(__half2*)&v.x);
        float2 fb = __half22float2(*(__half2*)&v.y);
        acc.x += ps * fa.x; acc.y += ps * fa.y;
        acc.z += ps * fb.x; acc.w += ps * fb.y;
    }
    float inv = 1.f / z;
    float4 bv = *(const float4*)&b1[lane * 4];
    float4 o;
    o.x = elu1(acc.x * inv + bv.x);
    o.y = elu1(acc.y * inv + bv.y);
    o.z = elu1(acc.z * inv + bv.z);
    o.w = elu1(acc.w * inv + bv.w);
    *(float4*)&g_h1[(size_t)n * 128 + lane * 4] = o;
}

// ---------------- GEMM2 + fused attention dots (layer 2) --------------------
__global__ void k_gemm2(const float* __restrict__ W2,
                        const float* __restrict__ a2s, const float* __restrict__ a2d) {
    __shared__ float Ws[128 * 32];
    int tid = threadIdx.x;
    for (int i = tid; i < 128 * 32; i += 256) Ws[i] = W2[i];
    __syncthreads();
    int n = blockIdx.x * 32 + (tid >> 3);
    int c4 = (tid & 7) * 4;
    const float* hrow = &g_h1[(size_t)n * 128];
    float4 acc = make_float4(0, 0, 0, 0);
#pragma unroll 8
    for (int k = 0; k < 128; k++) {
        float hv = __ldg(&hrow[k]);
        float4 w = *(float4*)&Ws[k * 32 + c4];
        acc.x += hv * w.x;
        acc.y += hv * w.y;
        acc.z += hv * w.z;
        acc.w += hv * w.w;
    }
    *(float4*)&g_h2f[(size_t)n * 32 + c4] = acc;
    float4 vs = *(const float4*)&a2s[c4];
    float4 vd = *(const float4*)&a2d[c4];
    float ss = acc.x * vs.x + acc.y * vs.y + acc.z * vs.z + acc.w * vs.w;
    float sd = acc.x * vd.x + acc.y * vd.y + acc.z * vd.z + acc.w * vd.w;
#pragma unroll
    for (int off = 1; off < 8; off <<= 1) {
        ss += __shfl_xor_sync(FULL, ss, off);
        sd += __shfl_xor_sync(FULL, sd, off);
    }
    if ((tid & 7) == 0) { g_als2[n] = ss; g_ald2[n] = sd; }
}

// ---------------- layer-2 fused softmax gather + alpha output ----------------
__global__ void __launch_bounds__(256) k_gather2(const float* __restrict__ b2,
                                                 float* __restrict__ out_h2,
                                                 float* __restrict__ out_alpha) {
    int n = (blockIdx.x * 256 + threadIdx.x) >> 5;
    int lane = threadIdx.x & 31;
    if (n >= NN) return;
    int beg = g_rs[n], end = g_rs[n + 1];
    int deg = end - beg;
    float ald  = g_ald2[n];
    float alsn = g_als2[n];
    float acc = 0.f, z = 0.f, sumae = 0.f;

    if (deg <= 32) {
        int m = deg;
        int sl = 0, el = 0;
        float p = 0.f;
        if (lane < m) {
            int2 se = g_cse[beg + lane];
            sl = se.x; el = se.y;
            float ae = __ldg(&g_ae2[el]);
            float als = __ldg(&g_als2[sl]);
            p = __expf(lrelu(als + ald + ae));
            sumae = ae;
        }
        for (int j = 0; j < m; j++) {
            int s = __shfl_sync(FULL, sl, j);
            float pj = __shfl_sync(FULL, p, j);
            z += pj;
            acc += pj * __ldg(&g_h2f[(size_t)s * 32 + lane]);
        }
#pragma unroll
        for (int off = 16; off; off >>= 1) sumae += __shfl_xor_sync(FULL, sumae, off);
        float slae = sumae / fmaxf((float)deg, 1.f);
        float ps = __expf(lrelu(alsn + ald + slae));
        z += ps;
        acc += ps * g_h2f[(size_t)n * 32 + lane];
        float invz = 1.f / z;
        if (lane < m) out_alpha[el] = p * invz;
        if (lane == 0) out_alpha[EE + n] = ps * invz;
        out_h2[(size_t)n * 32 + lane] = elu1(acc * invz + b2[lane]);
    } else {
        for (int base = beg; base < end; base += 32) {
            int m = end - base; if (m > 32) m = 32;
            int sl = 0;
            float p = 0.f;
            if (lane < m) {
                int2 se = g_cse[base + lane];
                sl = se.x;
                float ae = __ldg(&g_ae2[se.y]);
                float als = __ldg(&g_als2[sl]);
                p = __expf(lrelu(als + ald + ae));
                sumae += ae;
            }
            for (int j = 0; j < m; j++) {
                int s = __shfl_sync(FULL, sl, j);
                float pj = __shfl_sync(FULL, p, j);
                z += pj;
                acc += pj * __ldg(&g_h2f[(size_t)s * 32 + lane]);
            }
        }
#pragma unroll
        for (int off = 16; off; off >>= 1) sumae += __shfl_xor_sync(FULL, sumae, off);
        float slae = sumae / fmaxf((float)deg, 1.f);
        float ps = __expf(lrelu(alsn + ald + slae));
        z += ps;
        acc += ps * g_h2f[(size_t)n * 32 + lane];
        float invz = 1.f / z;
        for (int base = beg; base < end; base += 32) {
            int m = end - base; if (m > 32) m = 32;
            if (lane < m) {
                int2 se = g_cse[base + lane];
                float p = __expf(lrelu(__ldg(&g_als2[se.x]) + ald + __ldg(&g_ae2[se.y])));
                out_alpha[se.y] = p * invz;
            }
        }
        if (lane == 0) out_alpha[EE + n] = ps * invz;
        out_h2[(size_t)n * 32 + lane] = elu1(acc * invz + b2[lane]);
    }
}

// ---------------- launcher ---------------------------------------------------
static inline int dgrid(long n, int b) { return (int)((n + b - 1) / b); }

extern "C" void kernel_launch(void* const* d_in, const int* in_sizes, int n_in,
                              void* d_out, int out_size) {
    const float* x     = (const float*)d_in[0];
    const int*   ei    = (const int*)d_in[1];
    const int*   src   = ei;
    const int*   dst   = ei + EE;
    const float* eattr = (const float*)d_in[2];
    const float* W1    = (const float*)d_in[3];
    const float* W1e   = (const float*)d_in[4];
    const float* a1s   = (const float*)d_in[5];
    const float* a1d   = (const float*)d_in[6];
    const float* a1e   = (const float*)d_in[7];
    const float* b1    = (const float*)d_in[8];
    const float* W2    = (const float*)d_in[9];
    const float* W2e   = (const float*)d_in[10];
    const float* a2s   = (const float*)d_in[11];
    const float* a2d   = (const float*)d_in[12];
    const float* a2e   = (const float*)d_in[13];
    const float* b2    = (const float*)d_in[14];

    float* out       = (float*)d_out;
    float* out_h2    = out;                                  // N*32
    float* out_ei    = out + (size_t)NN * CC;                // 2*EPt
    float* out_alpha = out_ei + 2 * (size_t)EPt;             // EPt

    void* p;
    cudaGetSymbolAddress(&p, g_cnt);
    cudaMemsetAsync(p, 0, (size_t)2 * NN * 4);

    k_pre<<<dgrid(EPt, 256), 256>>>(eattr, src, dst, W1e, a1e, W2e, a2e, out_ei);
    k_scan<<<1, 1024>>>();
    k_fill<<<dgrid(EE, 256), 256>>>(src, dst);
    k_gemm1<<<dgrid(NN, 128), 256>>>(x, W1, a1s, a1d);
    k_gather1<<<dgrid((long)NN * 32, 256), 256>>>(b1);
    k_gemm2<<<NN / 32, 256>>>(W2, a2s, a2d);
    k_gather2<<<dgrid((long)NN * 32, 256), 256>>>(b2, out_h2, out_alpha);
}